// round 6
// baseline (speedup 1.0000x reference)
#include <cuda_runtime.h>
#include <cuda_bf16.h>
#include <cstdint>

// ---------------- problem constants ----------------
#define BB   4
#define NQ   8192
#define DM   256
#define HH   8
#define LL   4
#define DHD  32
#define NVV  5440
#define PCOLS 288
#define K3   768          // split-K: [A_hi | A_lo | A_hi] x [W_hi ; W_hi ; W_lo]
#define NITER 24          // 768 / 32
#define BK   32

__device__ __constant__ int   c_Wl[LL]   = {64, 32, 16, 8};
__device__ __constant__ int   c_lsi[LL]  = {0, 4096, 5120, 5376};
__device__ __constant__ float c_inv[LL]  = {1.f/64.f, 1.f/32.f, 1.f/16.f, 1.f/8.f};

// ---------------- static device scratch ----------------
__device__ __nv_bfloat16 g_Abig[32768 * K3];   // split-bf16 A (reused by all 3 GEMMs)
__device__ __nv_bfloat16 g_WbigT[384 * K3];    // split-bf16 W^T (N-major), padded to 384 rows
__device__ float g_v[BB * NVV * DM];
__device__ float g_P[BB * NQ * PCOLS];
__device__ float g_Wcat[DM * PCOLS];
__device__ float g_bcat[PCOLS];

// ---------------- helpers ----------------
__device__ __forceinline__ uint32_t smem_u32(const void* p) {
    uint32_t a;
    asm("{ .reg .u64 t; cvta.to.shared.u64 t, %1; cvt.u32.u64 %0, t; }" : "=r"(a) : "l"(p));
    return a;
}
__device__ __forceinline__ void cpa16(uint32_t s, const void* g) {
    asm volatile("cp.async.cg.shared.global [%0], [%1], 16;" :: "r"(s), "l"(g));
}
#define CPA_COMMIT() asm volatile("cp.async.commit_group;" ::: "memory")
#define SWZ64(x) ((x) ^ (((x) >> 3) & 0x30))

__device__ __forceinline__ void ldsm4(uint32_t& r0, uint32_t& r1, uint32_t& r2, uint32_t& r3,
                                      uint32_t addr) {
    asm volatile("ldmatrix.sync.aligned.m8n8.x4.shared.b16 {%0,%1,%2,%3}, [%4];"
                 : "=r"(r0), "=r"(r1), "=r"(r2), "=r"(r3) : "r"(addr));
}
__device__ __forceinline__ void mma16816(float* c, uint32_t a0, uint32_t a1, uint32_t a2,
                                         uint32_t a3, uint32_t b0, uint32_t b1) {
    asm volatile("mma.sync.aligned.m16n8k16.row.col.f32.bf16.bf16.f32 "
                 "{%0,%1,%2,%3}, {%4,%5,%6,%7}, {%8,%9}, {%0,%1,%2,%3};"
                 : "+f"(c[0]), "+f"(c[1]), "+f"(c[2]), "+f"(c[3])
                 : "r"(a0), "r"(a1), "r"(a2), "r"(a3), "r"(b0), "r"(b1));
}

// ---------------- pack projection weights [256 x 288] ----------------
__global__ void pack_kernel(const float* __restrict__ Wt, const float* __restrict__ bt,
                            const float* __restrict__ Wf, const float* __restrict__ bf,
                            const float* __restrict__ Wl, const float* __restrict__ bl,
                            const float* __restrict__ Wp, const float* __restrict__ bp) {
    int i = blockIdx.x * blockDim.x + threadIdx.x;
    if (i < DM * PCOLS) {
        int r = i / PCOLS, c = i % PCOLS;
        float v;
        if      (c < 64)  v = Wt[r * 64  + c];
        else if (c < 128) v = Wf[r * 64  + (c - 64)];
        else if (c < 160) v = Wl[r * 32  + (c - 128)];
        else              v = Wp[r * 128 + (c - 160)];
        g_Wcat[i] = v;
    }
    if (i < PCOLS) {
        float v;
        if      (i < 64)  v = bt[i];
        else if (i < 128) v = bf[i - 64];
        else if (i < 160) v = bl[i - 128];
        else              v = bp[i - 160];
        g_bcat[i] = v;
    }
}

// ---------------- fp32 -> split-bf16 conversions ----------------
__global__ void convA_kernel(const float* __restrict__ A, int total) {
    int i = blockIdx.x * blockDim.x + threadIdx.x;
    if (i >= total) return;
    int r = i >> 8, c = i & 255;
    float v = A[i];
    __nv_bfloat16 hi = __float2bfloat16(v);
    __nv_bfloat16 lo = __float2bfloat16(v - __bfloat162float(hi));
    size_t base = (size_t)r * K3 + c;
    g_Abig[base]       = hi;
    g_Abig[base + 256] = lo;
    g_Abig[base + 512] = hi;
}

// W is [256 x N] row-major; produce W^T split [384 x 768] (rows n>=N zero)
__global__ void convW_kernel(const float* __restrict__ W, int N) {
    int i = blockIdx.x * blockDim.x + threadIdx.x;
    if (i >= 384 * 256) return;
    int n = i >> 8, k = i & 255;
    float v = (n < N) ? W[k * N + n] : 0.f;
    __nv_bfloat16 hi = __float2bfloat16(v);
    __nv_bfloat16 lo = __float2bfloat16(v - __bfloat162float(hi));
    size_t base = (size_t)n * K3 + k;
    g_WbigT[base]       = hi;
    g_WbigT[base + 256] = hi;
    g_WbigT[base + 512] = lo;
}

// ---------------- bf16 mma.sync GEMM: C[M,N] = Abig[M,768] * WbigT^T + bias ----------------
// 128x128 tile, BK=32, 3-stage cp.async pipeline (48 KB smem), 8 warps (4M x 2N),
// warp tile 32x64, m16n8k16 HMMA, fp32 accumulate.   (round-4 proven version)
__global__ __launch_bounds__(256, 2)
void gemm_mma(const __nv_bfloat16* __restrict__ A,
              const float* __restrict__ bias, float* __restrict__ C,
              int M, int N) {
    extern __shared__ char smem[];                  // 3 * 16384
    const uint32_t sb = smem_u32(smem);
    const int tid = threadIdx.x, wid = tid >> 5, lane = tid & 31;
    const int wm = wid >> 1, wn = wid & 1;
    const int rowBase = blockIdx.y * 128, colBase = blockIdx.x * 128;

    const __nv_bfloat16* __restrict__ Bt = g_WbigT;

    auto load = [&](int j, int s) {
        uint32_t abase = sb + s * 16384;
        uint32_t bbase = abase + 8192;
        const __nv_bfloat16* ga = A  + (size_t)rowBase * K3 + j * BK;
        const __nv_bfloat16* gb = Bt + (size_t)colBase * K3 + j * BK;
#pragma unroll
        for (int it = 0; it < 2; it++) {
            int id = tid + it * 256;                // 0..511
            int r = id >> 2, c4 = (id & 3) * 16;    // byte col
            uint32_t sw = SWZ64(r * 64 + c4);
            cpa16(abase + sw, (const char*)(ga + (size_t)r * K3) + c4);
            cpa16(bbase + sw, (const char*)(gb + (size_t)r * K3) + c4);
        }
        CPA_COMMIT();
    };

    float acc[2][8][4];
#pragma unroll
    for (int mi = 0; mi < 2; mi++)
#pragma unroll
        for (int ni = 0; ni < 8; ni++)
#pragma unroll
            for (int q = 0; q < 4; q++) acc[mi][ni][q] = 0.f;

    load(0, 0); load(1, 1);

    const int aRow = (lane & 15);
    const int aK   = (lane >> 4) << 3;
    const int bRow = (lane & 7) + ((lane >> 4) << 3);
    const int bK   = ((lane >> 3) & 1) << 3;

    for (int i = 0; i < NITER; i++) {
        asm volatile("cp.async.wait_group 1;" ::: "memory");
        __syncthreads();
        if (i + 2 < NITER) load(i + 2, (i + 2) % 3);
        else CPA_COMMIT();

        uint32_t abase = sb + (i % 3) * 16384;
        uint32_t bbase = abase + 8192;
#pragma unroll
        for (int kk = 0; kk < BK; kk += 16) {
            uint32_t a[2][4];
#pragma unroll
            for (int mi = 0; mi < 2; mi++) {
                int row = wm * 32 + mi * 16 + aRow;
                int kb  = (kk + aK) * 2;
                ldsm4(a[mi][0], a[mi][1], a[mi][2], a[mi][3],
                      abase + SWZ64(row * 64 + kb));
            }
            uint32_t b[4][4];
#pragma unroll
            for (int ng = 0; ng < 4; ng++) {
                int row = wn * 64 + ng * 16 + bRow;
                int kb  = (kk + bK) * 2;
                ldsm4(b[ng][0], b[ng][1], b[ng][2], b[ng][3],
                      bbase + SWZ64(row * 64 + kb));
            }
#pragma unroll
            for (int mi = 0; mi < 2; mi++)
#pragma unroll
                for (int ni = 0; ni < 8; ni++) {
                    int ng = ni >> 1, half = ni & 1;
                    mma16816(acc[mi][ni], a[mi][0], a[mi][1], a[mi][2], a[mi][3],
                             b[ng][half * 2], b[ng][half * 2 + 1]);
                }
        }
        __syncthreads();
    }

    const int g = lane >> 2, tig = lane & 3;
#pragma unroll
    for (int mi = 0; mi < 2; mi++) {
        int r0 = rowBase + wm * 32 + mi * 16 + g;
        int r1 = r0 + 8;
#pragma unroll
        for (int ni = 0; ni < 8; ni++) {
            int c = colBase + wn * 64 + ni * 8 + tig * 2;
            if (c < N) {
                float bx = __ldg(&bias[c]), by = __ldg(&bias[c + 1]);
                float2 v0 = make_float2(acc[mi][ni][0] + bx, acc[mi][ni][1] + by);
                float2 v1 = make_float2(acc[mi][ni][2] + bx, acc[mi][ni][3] + by);
                *reinterpret_cast<float2*>(C + (size_t)r0 * N + c) = v0;
                *reinterpret_cast<float2*>(C + (size_t)r1 * N + c) = v1;
            }
        }
    }
}

// ---------------- deformable sampling: cell dedup + MLP-8 gather ----------------
__device__ __forceinline__ float tanh_approx(float x) {
    float r;
    asm("tanh.approx.f32 %0, %1;" : "=f"(r) : "f"(x));
    return r;
}

// one warp per (b,q,h). lanes 0..3 each build the merged product-cell list for one
// level (exact reassociation of the 16 bilinear taps; avg ~9 cells/level), lists are
// compacted + padded to a multiple of 8, then all 32 lanes gather in unroll-8
// batches of independent loads (lane = channel within head).
__global__ __launch_bounds__(256)
void sample_kernel(const float* __restrict__ refp) {
    __shared__ int    t_idx[8][64];
    __shared__ float  t_w[8][64];
    __shared__ float2 s_tap[8][64];     // .x = weight, .y = index bits
    __shared__ int    s_cnt[8][5];

    const int warp = threadIdx.x >> 5;
    const int lane = threadIdx.x & 31;
    const int gid = blockIdx.x * 8 + warp;            // 0..B*NQ*H-1
    const int h  = gid & (HH - 1);
    const int bq = gid >> 3;
    const int b  = bq >> 13;                          // NQ=8192

    const float* __restrict__ P  = g_P + (size_t)bq * PCOLS;
    const float* __restrict__ rp = refp + (size_t)bq * (LL * 2);
    const int hL = h * LL;

    if (lane < 4) {
        const int l = lane;
        const int Wi = c_Wl[l];
        const float Wf = (float)Wi;
        const float inv = c_inv[l];
        const int start = c_lsi[l];

        // level softmax -> weight of this level
        float e0 = P[128 + hL + 0], e1 = P[128 + hL + 1];
        float e2 = P[128 + hL + 2], e3 = P[128 + hL + 3];
        float mx = fmaxf(fmaxf(e0, e1), fmaxf(e2, e3));
        float x0e = __expf(e0 - mx), x1e = __expf(e1 - mx);
        float x2e = __expf(e2 - mx), x3e = __expf(e3 - mx);
        float lw = (l == 0 ? x0e : l == 1 ? x1e : l == 2 ? x2e : x3e)
                   * __frcp_rn(x0e + x1e + x2e + x3e);

        // point softmax pw[kt*2+kf]
        const float* pp = P + 160 + (hL + l) * 4;
        float p0 = pp[0], p1 = pp[1], p2 = pp[2], p3 = pp[3];
        float pm = fmaxf(fmaxf(p0, p1), fmaxf(p2, p3));
        float q0 = __expf(p0 - pm), q1 = __expf(p1 - pm);
        float q2 = __expf(p2 - pm), q3 = __expf(p3 - pm);
        float pinv = __frcp_rn(q0 + q1 + q2 + q3);
        q0 *= pinv; q1 *= pinv; q2 *= pinv; q3 *= pinv;

        // merged x-cell list (time offsets), per-kt weights kept separate
        int   xc[4]; float xw0[4], xw1[4]; int nx = 0;
        int   yc[4]; float yw0[4], yw1[4]; int ny = 0;
#pragma unroll
        for (int kt = 0; kt < 2; kt++) {
            float t = tanh_approx(P[(hL + l) * 2 + kt]);
            float lx = fminf(fmaxf(rp[l * 2 + 0] + t * inv, 0.f), 1.f);
            float x = lx * Wf - 0.5f;
            float cf = floorf(x);
            float fx = x - cf;
            int c0 = (int)cf;
#pragma unroll
            for (int s = 0; s < 2; s++) {
                int c = c0 + s;
                float w = s ? fx : (1.f - fx);
                if (c >= 0 && c < Wi) {
                    bool found = false;
                    for (int i = 0; i < nx; i++)
                        if (xc[i] == c) { if (kt) xw1[i] += w; else xw0[i] += w; found = true; }
                    if (!found) {
                        xc[nx] = c;
                        xw0[nx] = kt ? 0.f : w;
                        xw1[nx] = kt ? w : 0.f;
                        nx++;
                    }
                }
            }
        }
#pragma unroll
        for (int kf = 0; kf < 2; kf++) {
            float f = tanh_approx(P[64 + (hL + l) * 2 + kf]);
            float ly = fminf(fmaxf(rp[l * 2 + 1] + f * inv, 0.f), 1.f);
            float y = ly * Wf - 0.5f;
            float cf = floorf(y);
            float fy = y - cf;
            int c0 = (int)cf;
#pragma unroll
            for (int s = 0; s < 2; s++) {
                int c = c0 + s;
                float w = s ? fy : (1.f - fy);
                if (c >= 0 && c < Wi) {
                    bool found = false;
                    for (int i = 0; i < ny; i++)
                        if (yc[i] == c) { if (kf) yw1[i] += w; else yw0[i] += w; found = true; }
                    if (!found) {
                        yc[ny] = c;
                        yw0[ny] = kf ? 0.f : w;
                        yw1[ny] = kf ? w : 0.f;
                        ny++;
                    }
                }
            }
        }
        // emit product cells: weight = lw * (xw0*(yw0*q0 + yw1*q1) + xw1*(yw0*q2 + yw1*q3))
        int cnt = 0;
        for (int i = 0; i < nx; i++) {
            float wx0 = xw0[i], wx1 = xw1[i];
            int xcc = start + xc[i];
            for (int j = 0; j < ny; j++) {
                float w = lw * (wx0 * (yw0[j] * q0 + yw1[j] * q1)
                              + wx1 * (yw0[j] * q2 + yw1[j] * q3));
                t_idx[warp][l * 16 + cnt] = xcc + yc[j] * Wi;
                t_w[warp][l * 16 + cnt]   = w;
                cnt++;
            }
        }
        s_cnt[warp][l] = cnt;
    }
    __syncwarp();

    // compact + pad to multiple of 8
    if (lane < 4) {
        int c0 = s_cnt[warp][0], c1 = s_cnt[warp][1], c2 = s_cnt[warp][2];
        int pre = (lane > 0 ? c0 : 0) + (lane > 1 ? c1 : 0) + (lane > 2 ? c2 : 0);
        int cnt = s_cnt[warp][lane];
        for (int i = 0; i < cnt; i++)
            s_tap[warp][pre + i] = make_float2(t_w[warp][lane * 16 + i],
                                               __int_as_float(t_idx[warp][lane * 16 + i]));
        if (lane == 3) {
            int total = pre + cnt;
            int padded = (total + 7) & ~7;
            for (int i = total; i < padded; i++)
                s_tap[warp][i] = make_float2(0.f, __int_as_float(0));
            s_cnt[warp][4] = padded;
        }
    }
    __syncwarp();

    const int total = s_cnt[warp][4];
    const float* __restrict__ vb = g_v + (size_t)b * NVV * DM + h * DHD + lane;
    float acc = 0.f;
    for (int t = 0; t < total; t += 8) {
        float wv[8], vv[8];
        const float* pt[8];
#pragma unroll
        for (int j = 0; j < 8; j++) {
            float2 tp = s_tap[warp][t + j];
            wv[j] = tp.x;
            pt[j] = vb + (size_t)__float_as_int(tp.y) * DM;
        }
#pragma unroll
        for (int j = 0; j < 8; j++) vv[j] = *pt[j];      // 8 independent LDGs in flight
#pragma unroll
        for (int j = 0; j < 8; j++) acc += wv[j] * vv[j];
    }

    // write directly as split-bf16 into Abig for the output GEMM
    const int col = h * DHD + lane;
    size_t base = (size_t)bq * K3 + col;
    __nv_bfloat16 hi = __float2bfloat16(acc);
    __nv_bfloat16 lo = __float2bfloat16(acc - __bfloat162float(hi));
    g_Abig[base]       = hi;
    g_Abig[base + 256] = lo;
    g_Abig[base + 512] = hi;
}

// ---------------- launch ----------------
extern "C" void kernel_launch(void* const* d_in, const int* in_sizes, int n_in,
                              void* d_out, int out_size) {
    const float* query  = (const float*)d_in[0];
    const float* refp   = (const float*)d_in[1];
    const float* value  = (const float*)d_in[2];
    const float* W_time = (const float*)d_in[5];
    const float* b_time = (const float*)d_in[6];
    const float* W_freq = (const float*)d_in[7];
    const float* b_freq = (const float*)d_in[8];
    const float* W_lvl  = (const float*)d_in[9];
    const float* b_lvl  = (const float*)d_in[10];
    const float* W_pt   = (const float*)d_in[11];
    const float* b_pt   = (const float*)d_in[12];
    const float* W_v    = (const float*)d_in[13];
    const float* b_v    = (const float*)d_in[14];
    const float* W_o    = (const float*)d_in[15];
    const float* b_o    = (const float*)d_in[16];
    float* out = (float*)d_out;

    float *p_v, *p_P, *p_Wcat, *p_bcat;
    __nv_bfloat16* p_Abig;
    cudaGetSymbolAddress((void**)&p_v,    g_v);
    cudaGetSymbolAddress((void**)&p_P,    g_P);
    cudaGetSymbolAddress((void**)&p_Wcat, g_Wcat);
    cudaGetSymbolAddress((void**)&p_bcat, g_bcat);
    cudaGetSymbolAddress((void**)&p_Abig, g_Abig);

    const int GEMM_SMEM = 3 * 16384;   // 48 KB — within default dynamic smem limit

    // 1) pack Wcat (fp32)
    pack_kernel<<<(DM * PCOLS + 255) / 256, 256>>>(W_time, b_time, W_freq, b_freq,
                                                   W_lvl, b_lvl, W_pt, b_pt);

    // 2) value GEMM: g_v = value @ W_v + b_v   [21760 x 256]
    convW_kernel<<<(384 * 256 + 255) / 256, 256>>>(W_v, DM);
    convA_kernel<<<(BB * NVV * DM + 255) / 256, 256>>>(value, BB * NVV * DM);
    {
        dim3 grid(2, (BB * NVV) / 128);
        gemm_mma<<<grid, 256, GEMM_SMEM>>>(p_Abig, b_v, p_v, BB * NVV, DM);
    }

    // 3) query projections: g_P = query @ Wcat + bcat   [32768 x 288]
    convW_kernel<<<(384 * 256 + 255) / 256, 256>>>(p_Wcat, PCOLS);
    convA_kernel<<<(BB * NQ * DM + 255) / 256, 256>>>(query, BB * NQ * DM);
    {
        dim3 grid(3, (BB * NQ) / 128);
        gemm_mma<<<grid, 256, GEMM_SMEM>>>(p_Abig, p_bcat, p_P, BB * NQ, PCOLS);
    }

    // 4) deformable sampling (merged cells, MLP-8 gather) -> split-bf16 mid in Abig
    sample_kernel<<<(BB * NQ * HH) / 8, 256>>>(refp);

    // 5) output GEMM: out = mid @ W_o + b_o   [32768 x 256]
    convW_kernel<<<(384 * 256 + 255) / 256, 256>>>(W_o, DM);
    {
        dim3 grid(2, (BB * NQ) / 128);
        gemm_mma<<<grid, 256, GEMM_SMEM>>>(p_Abig, b_o, out, BB * NQ, DM);
    }
}

// round 7
// speedup vs baseline: 1.5146x; 1.5146x over previous
#include <cuda_runtime.h>
#include <cuda_bf16.h>
#include <cstdint>

// ---------------- problem constants ----------------
#define BB   4
#define NQ   8192
#define DM   256
#define HH   8
#define LL   4
#define DHD  32
#define NVV  5440
#define PCOLS 288
#define K3   768          // split-K: [A_hi | A_lo | A_hi] x [W_hi ; W_hi ; W_lo]
#define NITER 24          // 768 / 32
#define BK   32
#define VTILES 340        // value GEMM: 170 row-tiles x 2 col-tiles

__device__ __constant__ int   c_Wl[LL]   = {64, 32, 16, 8};
__device__ __constant__ int   c_lsi[LL]  = {0, 4096, 5120, 5376};
__device__ __constant__ float c_inv[LL]  = {1.f/64.f, 1.f/32.f, 1.f/16.f, 1.f/8.f};

// ---------------- static device scratch ----------------
__device__ __nv_bfloat16 g_Abig[32768 * K3];   // split-bf16 A (query, then mid)
__device__ __nv_bfloat16 g_AV[BB * NVV * K3];  // split-bf16 A (value)
__device__ __nv_bfloat16 g_WTV[384 * K3];      // split W^T for W_v (reused for W_o)
__device__ __nv_bfloat16 g_WTQ[384 * K3];      // split W^T for Wcat
__device__ float g_v[BB * NVV * DM];
__device__ float g_P[BB * NQ * PCOLS];
__device__ float g_bcat[PCOLS];

// ---------------- helpers ----------------
__device__ __forceinline__ uint32_t smem_u32(const void* p) {
    uint32_t a;
    asm("{ .reg .u64 t; cvta.to.shared.u64 t, %1; cvt.u32.u64 %0, t; }" : "=r"(a) : "l"(p));
    return a;
}
__device__ __forceinline__ void cpa16(uint32_t s, const void* g) {
    asm volatile("cp.async.cg.shared.global [%0], [%1], 16;" :: "r"(s), "l"(g));
}
#define CPA_COMMIT() asm volatile("cp.async.commit_group;" ::: "memory")
#define SWZ64(x) ((x) ^ (((x) >> 3) & 0x30))

__device__ __forceinline__ void ldsm4(uint32_t& r0, uint32_t& r1, uint32_t& r2, uint32_t& r3,
                                      uint32_t addr) {
    asm volatile("ldmatrix.sync.aligned.m8n8.x4.shared.b16 {%0,%1,%2,%3}, [%4];"
                 : "=r"(r0), "=r"(r1), "=r"(r2), "=r"(r3) : "r"(addr));
}
__device__ __forceinline__ void mma16816(float* c, uint32_t a0, uint32_t a1, uint32_t a2,
                                         uint32_t a3, uint32_t b0, uint32_t b1) {
    asm volatile("mma.sync.aligned.m16n8k16.row.col.f32.bf16.bf16.f32 "
                 "{%0,%1,%2,%3}, {%4,%5,%6,%7}, {%8,%9}, {%0,%1,%2,%3};"
                 : "+f"(c[0]), "+f"(c[1]), "+f"(c[2]), "+f"(c[3])
                 : "r"(a0), "r"(a1), "r"(a2), "r"(a3), "r"(b0), "r"(b1));
}

// ---------------- fp32 -> split-bf16 conversions ----------------
__global__ void convA_kernel(const float* __restrict__ A, __nv_bfloat16* __restrict__ dst,
                             int total) {
    int i = blockIdx.x * blockDim.x + threadIdx.x;
    if (i >= total) return;
    int r = i >> 8, c = i & 255;
    float v = A[i];
    __nv_bfloat16 hi = __float2bfloat16(v);
    __nv_bfloat16 lo = __float2bfloat16(v - __bfloat162float(hi));
    size_t base = (size_t)r * K3 + c;
    dst[base]       = hi;
    dst[base + 256] = lo;
    dst[base + 512] = hi;
}

// W is [256 x N] row-major; produce W^T split [384 x 768] (rows n>=N zero)
__global__ void convW_kernel(const float* __restrict__ W, __nv_bfloat16* __restrict__ dst,
                             int N) {
    int i = blockIdx.x * blockDim.x + threadIdx.x;
    if (i >= 384 * 256) return;
    int n = i >> 8, k = i & 255;
    float v = (n < N) ? W[k * N + n] : 0.f;
    __nv_bfloat16 hi = __float2bfloat16(v);
    __nv_bfloat16 lo = __float2bfloat16(v - __bfloat162float(hi));
    size_t base = (size_t)n * K3 + k;
    dst[base]       = hi;
    dst[base + 256] = hi;
    dst[base + 512] = lo;
}

// build split W^T for the concatenated projection weights directly + bias
__global__ void convWcat_kernel(const float* __restrict__ Wt, const float* __restrict__ bt,
                                const float* __restrict__ Wf, const float* __restrict__ bf,
                                const float* __restrict__ Wl, const float* __restrict__ bl,
                                const float* __restrict__ Wp, const float* __restrict__ bp) {
    int i = blockIdx.x * blockDim.x + threadIdx.x;
    if (i < 384 * 256) {
        int n = i >> 8, k = i & 255;
        float v = 0.f;
        if      (n < 64)    v = Wt[k * 64  + n];
        else if (n < 128)   v = Wf[k * 64  + (n - 64)];
        else if (n < 160)   v = Wl[k * 32  + (n - 128)];
        else if (n < PCOLS) v = Wp[k * 128 + (n - 160)];
        __nv_bfloat16 hi = __float2bfloat16(v);
        __nv_bfloat16 lo = __float2bfloat16(v - __bfloat162float(hi));
        size_t base = (size_t)n * K3 + k;
        g_WTQ[base]       = hi;
        g_WTQ[base + 256] = hi;
        g_WTQ[base + 512] = lo;
    }
    if (i < PCOLS) {
        float v;
        if      (i < 64)  v = bt[i];
        else if (i < 128) v = bf[i - 64];
        else if (i < 160) v = bl[i - 128];
        else              v = bp[i - 160];
        g_bcat[i] = v;
    }
}

// ---------------- GEMM tile body: 128x128, BK=32, 4-stage cp.async ----------------
// 8 warps (4M x 2N), warp tile 32x64, m16n8k16 HMMA, fp32 accumulate.
__device__ __forceinline__ void gemm_body(const __nv_bfloat16* __restrict__ A,
                                          const __nv_bfloat16* __restrict__ Bt,
                                          const float* __restrict__ bias,
                                          float* __restrict__ C,
                                          int N, int rowBase, int colBase, uint32_t sb) {
    const int tid = threadIdx.x, wid = tid >> 5, lane = tid & 31;
    const int wm = wid >> 1, wn = wid & 1;

    auto load = [&](int j, int s) {
        uint32_t abase = sb + s * 16384;
        uint32_t bbase = abase + 8192;
        const __nv_bfloat16* ga = A  + (size_t)rowBase * K3 + j * BK;
        const __nv_bfloat16* gb = Bt + (size_t)colBase * K3 + j * BK;
#pragma unroll
        for (int it = 0; it < 2; it++) {
            int id = tid + it * 256;                // 0..511
            int r = id >> 2, c4 = (id & 3) * 16;
            uint32_t sw = SWZ64(r * 64 + c4);
            cpa16(abase + sw, (const char*)(ga + (size_t)r * K3) + c4);
            cpa16(bbase + sw, (const char*)(gb + (size_t)r * K3) + c4);
        }
        CPA_COMMIT();
    };

    float acc[2][8][4];
#pragma unroll
    for (int mi = 0; mi < 2; mi++)
#pragma unroll
        for (int ni = 0; ni < 8; ni++)
#pragma unroll
            for (int q = 0; q < 4; q++) acc[mi][ni][q] = 0.f;

    load(0, 0); load(1, 1); load(2, 2);

    const int aRow = (lane & 15);
    const int aK   = (lane >> 4) << 3;
    const int bRow = (lane & 7) + ((lane >> 4) << 3);
    const int bK   = ((lane >> 3) & 1) << 3;

    for (int i = 0; i < NITER; i++) {
        asm volatile("cp.async.wait_group 2;" ::: "memory");
        __syncthreads();
        if (i + 3 < NITER) load(i + 3, (i + 3) & 3);
        else CPA_COMMIT();                          // keep group accounting uniform

        uint32_t abase = sb + (i & 3) * 16384;
        uint32_t bbase = abase + 8192;
#pragma unroll
        for (int kk = 0; kk < BK; kk += 16) {
            uint32_t a[2][4];
#pragma unroll
            for (int mi = 0; mi < 2; mi++) {
                int row = wm * 32 + mi * 16 + aRow;
                ldsm4(a[mi][0], a[mi][1], a[mi][2], a[mi][3],
                      abase + SWZ64(row * 64 + (kk + aK) * 2));
            }
            uint32_t b[4][4];
#pragma unroll
            for (int ng = 0; ng < 4; ng++) {
                int row = wn * 64 + ng * 16 + bRow;
                ldsm4(b[ng][0], b[ng][1], b[ng][2], b[ng][3],
                      bbase + SWZ64(row * 64 + (kk + bK) * 2));
            }
#pragma unroll
            for (int mi = 0; mi < 2; mi++)
#pragma unroll
                for (int ni = 0; ni < 8; ni++) {
                    int ng = ni >> 1, half = ni & 1;
                    mma16816(acc[mi][ni], a[mi][0], a[mi][1], a[mi][2], a[mi][3],
                             b[ng][half * 2], b[ng][half * 2 + 1]);
                }
        }
    }

    const int g = lane >> 2, tig = lane & 3;
#pragma unroll
    for (int mi = 0; mi < 2; mi++) {
        int r0 = rowBase + wm * 32 + mi * 16 + g;
        int r1 = r0 + 8;
#pragma unroll
        for (int ni = 0; ni < 8; ni++) {
            int c = colBase + wn * 64 + ni * 8 + tig * 2;
            if (c < N) {
                float bx = __ldg(&bias[c]), by = __ldg(&bias[c + 1]);
                float2 v0 = make_float2(acc[mi][ni][0] + bx, acc[mi][ni][1] + by);
                float2 v1 = make_float2(acc[mi][ni][2] + bx, acc[mi][ni][3] + by);
                *reinterpret_cast<float2*>(C + (size_t)r0 * N + c) = v0;
                *reinterpret_cast<float2*>(C + (size_t)r1 * N + c) = v1;
            }
        }
    }
}

// fused value + query GEMM (independent -> one launch to amortize wave tails)
__global__ __launch_bounds__(256, 2)
void gemm_vq(const float* __restrict__ biasV, float* __restrict__ CV,
             float* __restrict__ CQ) {
    extern __shared__ char smem[];                  // 4 * 16384
    uint32_t sb = smem_u32(smem);
    int t = blockIdx.x;
    if (t < VTILES) {
        int rowBase = (t >> 1) * 128, colBase = (t & 1) * 128;
        gemm_body(g_AV, g_WTV, biasV, CV, DM, rowBase, colBase, sb);
    } else {
        t -= VTILES;
        int rowBase = (t / 3) * 128, colBase = (t % 3) * 128;
        gemm_body(g_Abig, g_WTQ, g_bcat, CQ, PCOLS, rowBase, colBase, sb);
    }
}

// single GEMM (output projection)
__global__ __launch_bounds__(256, 2)
void gemm_single(const __nv_bfloat16* __restrict__ A, const __nv_bfloat16* __restrict__ Bt,
                 const float* __restrict__ bias, float* __restrict__ C, int N) {
    extern __shared__ char smem[];
    uint32_t sb = smem_u32(smem);
    int tilesX = (N + 127) / 128;
    int rowBase = (blockIdx.x / tilesX) * 128, colBase = (blockIdx.x % tilesX) * 128;
    gemm_body(A, Bt, bias, C, N, rowBase, colBase, sb);
}

// ---------------- deformable sampling (round-4 proven version) ----------------
__device__ __forceinline__ float tanh_approx(float x) {
    float r;
    asm("tanh.approx.f32 %0, %1;" : "=f"(r) : "f"(x));
    return r;
}

// one warp per (b,q,h); lanes 0..15 precompute the 16 samples' taps; all 32 gather
__global__ __launch_bounds__(256)
void sample_kernel(const float* __restrict__ refp) {
    __shared__ int   s_idx[8][64];
    __shared__ float s_w[8][64];

    const int warp = threadIdx.x >> 5;
    const int lane = threadIdx.x & 31;
    const int gid = blockIdx.x * 8 + warp;            // 0..B*NQ*H-1
    const int h  = gid & (HH - 1);
    const int bq = gid >> 3;
    const int b  = bq >> 13;                          // NQ=8192

    const float* __restrict__ P = g_P + (size_t)bq * PCOLS;
    const int hL = h * LL;

    if (lane < 16) {
        const int l  = lane >> 2, k = lane & 3;
        const int kt = k >> 1,    kf = k & 1;
        const float t = tanh_approx(P[(hL + l) * 2 + kt]);
        const float f = tanh_approx(P[64 + (hL + l) * 2 + kf]);

        float e0 = P[128 + hL + 0], e1 = P[128 + hL + 1];
        float e2 = P[128 + hL + 2], e3 = P[128 + hL + 3];
        float mx = fmaxf(fmaxf(e0, e1), fmaxf(e2, e3));
        float x0e = __expf(e0 - mx), x1e = __expf(e1 - mx);
        float x2e = __expf(e2 - mx), x3e = __expf(e3 - mx);
        float lsum = x0e + x1e + x2e + x3e;
        float lwv = (l == 0 ? x0e : l == 1 ? x1e : l == 2 ? x2e : x3e);

        const float* pp = P + 160 + (hL + l) * 4;
        float p0 = pp[0], p1 = pp[1], p2 = pp[2], p3 = pp[3];
        float pm = fmaxf(fmaxf(p0, p1), fmaxf(p2, p3));
        float q0 = __expf(p0 - pm), q1 = __expf(p1 - pm);
        float q2 = __expf(p2 - pm), q3 = __expf(p3 - pm);
        float psum = q0 + q1 + q2 + q3;
        float pwv = (k == 0 ? q0 : k == 1 ? q1 : k == 2 ? q2 : q3);

        const float a = __fdividef(lwv * pwv, lsum * psum);

        const float* rp = refp + (size_t)bq * (LL * 2);
        const int   Wl = c_Wl[l];
        const int   start = c_lsi[l];
        const float fWl = (float)Wl;
        float lx = rp[l * 2 + 0] + t * c_inv[l];
        float ly = rp[l * 2 + 1] + f * c_inv[l];
        lx = fminf(fmaxf(lx, 0.f), 1.f);
        ly = fminf(fmaxf(ly, 0.f), 1.f);
        float x = lx * fWl - 0.5f;
        float y = ly * fWl - 0.5f;       // Hl == Wl for all levels
        float x0f = floorf(x), y0f = floorf(y);
        float wx1 = x - x0f, wy1 = y - y0f;
        float wx0 = 1.f - wx1, wy0 = 1.f - wy1;
        int x0 = (int)x0f, y0 = (int)y0f;

#pragma unroll
        for (int j = 0; j < 4; j++) {
            int xi = x0 + (j & 1), yi = y0 + (j >> 1);
            float w = a * ((j & 1) ? wx1 : wx0) * ((j >> 1) ? wy1 : wy0);
            bool valid = (xi >= 0) & (xi < Wl) & (yi >= 0) & (yi < Wl);
            int xc = min(max(xi, 0), Wl - 1);
            int yc = min(max(yi, 0), Wl - 1);
            s_idx[warp][lane * 4 + j] = start + yc * Wl + xc;
            s_w[warp][lane * 4 + j]   = valid ? w : 0.f;
        }
    }
    __syncwarp();

    const float* __restrict__ vb = g_v + (size_t)b * NVV * DM + h * DHD + lane;
    float acc = 0.f;
#pragma unroll 16
    for (int t = 0; t < 64; t++) {
        acc += s_w[warp][t] * vb[(size_t)s_idx[warp][t] * DM];
    }

    // write directly as split-bf16 into Abig for the output GEMM
    const int col = h * DHD + lane;
    size_t base = (size_t)bq * K3 + col;
    __nv_bfloat16 hi = __float2bfloat16(acc);
    __nv_bfloat16 lo = __float2bfloat16(acc - __bfloat162float(hi));
    g_Abig[base]       = hi;
    g_Abig[base + 256] = lo;
    g_Abig[base + 512] = hi;
}

// ---------------- launch ----------------
extern "C" void kernel_launch(void* const* d_in, const int* in_sizes, int n_in,
                              void* d_out, int out_size) {
    const float* query  = (const float*)d_in[0];
    const float* refp   = (const float*)d_in[1];
    const float* value  = (const float*)d_in[2];
    const float* W_time = (const float*)d_in[5];
    const float* b_time = (const float*)d_in[6];
    const float* W_freq = (const float*)d_in[7];
    const float* b_freq = (const float*)d_in[8];
    const float* W_lvl  = (const float*)d_in[9];
    const float* b_lvl  = (const float*)d_in[10];
    const float* W_pt   = (const float*)d_in[11];
    const float* b_pt   = (const float*)d_in[12];
    const float* W_v    = (const float*)d_in[13];
    const float* b_v    = (const float*)d_in[14];
    const float* W_o    = (const float*)d_in[15];
    const float* b_o    = (const float*)d_in[16];
    float* out = (float*)d_out;

    float *p_v, *p_P;
    __nv_bfloat16 *p_Abig, *p_AV, *p_WTV;
    cudaGetSymbolAddress((void**)&p_v,    g_v);
    cudaGetSymbolAddress((void**)&p_P,    g_P);
    cudaGetSymbolAddress((void**)&p_Abig, g_Abig);
    cudaGetSymbolAddress((void**)&p_AV,   g_AV);
    cudaGetSymbolAddress((void**)&p_WTV,  g_WTV);

    const int GEMM_SMEM = 4 * 16384;   // 64 KB
    cudaFuncSetAttribute(gemm_vq,     cudaFuncAttributeMaxDynamicSharedMemorySize, GEMM_SMEM);
    cudaFuncSetAttribute(gemm_single, cudaFuncAttributeMaxDynamicSharedMemorySize, GEMM_SMEM);

    // 1) weight conversions + A conversions (all independent)
    convW_kernel<<<(384 * 256 + 255) / 256, 256>>>(W_v, p_WTV, DM);
    convWcat_kernel<<<(384 * 256 + 255) / 256, 256>>>(W_time, b_time, W_freq, b_freq,
                                                      W_lvl, b_lvl, W_pt, b_pt);
    convA_kernel<<<(BB * NVV * DM + 255) / 256, 256>>>(value, p_AV, BB * NVV * DM);
    convA_kernel<<<(BB * NQ * DM + 255) / 256, 256>>>(query, p_Abig, BB * NQ * DM);

    // 2) fused value + query GEMMs (340 + 768 = 1108 CTAs)
    gemm_vq<<<VTILES + 768, 256, GEMM_SMEM>>>(b_v, p_v, p_P);

    // 3) deformable sampling -> split-bf16 mid into Abig
    sample_kernel<<<(BB * NQ * HH) / 8, 256>>>(refp);

    // 4) output GEMM: out = mid @ W_o + b_o   [32768 x 256]
    convW_kernel<<<(384 * 256 + 255) / 256, 256>>>(W_o, p_WTV, DM);
    gemm_single<<<512, 256, GEMM_SMEM>>>(p_Abig, p_WTV, b_o, out, DM);
}

// round 8
// speedup vs baseline: 1.5465x; 1.0211x over previous
#include <cuda_runtime.h>
#include <cuda_bf16.h>
#include <cstdint>

// ---------------- problem constants ----------------
#define BB   4
#define NQ   8192
#define DM   256
#define HH   8
#define LL   4
#define DHD  32
#define NVV  5440
#define PCOLS 288
#define K3   768          // logical split-K: [A_hi | A_lo | A_hi] x [W_hi ; W_hi ; W_lo]
#define ASTR 512          // physical A storage: [A_hi | A_lo], 512 cols
#define NITER 24          // 768 / 32
#define BK   32
#define VTILES 340        // value GEMM: 170 row-tiles x 2 col-tiles

__device__ __constant__ int   c_Wl[LL]   = {64, 32, 16, 8};
__device__ __constant__ int   c_lsi[LL]  = {0, 4096, 5120, 5376};
__device__ __constant__ float c_inv[LL]  = {1.f/64.f, 1.f/32.f, 1.f/16.f, 1.f/8.f};

// ---------------- static device scratch ----------------
__device__ __nv_bfloat16 g_Abig[32768 * ASTR];  // split-bf16 A (query, then mid)
__device__ __nv_bfloat16 g_AV[BB * NVV * ASTR]; // split-bf16 A (value)
__device__ __nv_bfloat16 g_WTV[384 * K3];       // split W^T for W_v (reused for W_o)
__device__ __nv_bfloat16 g_WTQ[384 * K3];       // split W^T for Wcat
__device__ float g_v[BB * NVV * DM];
__device__ float g_P[BB * NQ * PCOLS];
__device__ float g_bcat[PCOLS];

// ---------------- helpers ----------------
__device__ __forceinline__ uint32_t smem_u32(const void* p) {
    uint32_t a;
    asm("{ .reg .u64 t; cvta.to.shared.u64 t, %1; cvt.u32.u64 %0, t; }" : "=r"(a) : "l"(p));
    return a;
}
__device__ __forceinline__ void cpa16(uint32_t s, const void* g) {
    asm volatile("cp.async.cg.shared.global [%0], [%1], 16;" :: "r"(s), "l"(g));
}
#define CPA_COMMIT() asm volatile("cp.async.commit_group;" ::: "memory")
#define SWZ64(x) ((x) ^ (((x) >> 3) & 0x30))

__device__ __forceinline__ void ldsm4(uint32_t& r0, uint32_t& r1, uint32_t& r2, uint32_t& r3,
                                      uint32_t addr) {
    asm volatile("ldmatrix.sync.aligned.m8n8.x4.shared.b16 {%0,%1,%2,%3}, [%4];"
                 : "=r"(r0), "=r"(r1), "=r"(r2), "=r"(r3) : "r"(addr));
}
__device__ __forceinline__ void mma16816(float* c, uint32_t a0, uint32_t a1, uint32_t a2,
                                         uint32_t a3, uint32_t b0, uint32_t b1) {
    asm volatile("mma.sync.aligned.m16n8k16.row.col.f32.bf16.bf16.f32 "
                 "{%0,%1,%2,%3}, {%4,%5,%6,%7}, {%8,%9}, {%0,%1,%2,%3};"
                 : "+f"(c[0]), "+f"(c[1]), "+f"(c[2]), "+f"(c[3])
                 : "r"(a0), "r"(a1), "r"(a2), "r"(a3), "r"(b0), "r"(b1));
}

// chunk j (0..23) -> element offset inside the 512-col A storage
__device__ __forceinline__ int a_chunk_off(int j) {
    int jj = (j < 16) ? j : (j - 16);
    return ((jj & 8) ? 256 : 0) + (jj & 7) * BK;
}

// ---------------- fp32 -> split-bf16 conversions ----------------
__global__ void convA_kernel(const float* __restrict__ A, __nv_bfloat16* __restrict__ dst,
                             int total) {
    int i = blockIdx.x * blockDim.x + threadIdx.x;
    if (i >= total) return;
    int r = i >> 8, c = i & 255;
    float v = A[i];
    __nv_bfloat16 hi = __float2bfloat16(v);
    __nv_bfloat16 lo = __float2bfloat16(v - __bfloat162float(hi));
    size_t base = (size_t)r * ASTR + c;
    dst[base]       = hi;
    dst[base + 256] = lo;
}

// W is [256 x N] row-major; produce W^T split [384 x 768] (rows n>=N zero)
__global__ void convW_kernel(const float* __restrict__ W, __nv_bfloat16* __restrict__ dst,
                             int N) {
    int i = blockIdx.x * blockDim.x + threadIdx.x;
    if (i >= 384 * 256) return;
    int n = i >> 8, k = i & 255;
    float v = (n < N) ? W[k * N + n] : 0.f;
    __nv_bfloat16 hi = __float2bfloat16(v);
    __nv_bfloat16 lo = __float2bfloat16(v - __bfloat162float(hi));
    size_t base = (size_t)n * K3 + k;
    dst[base]       = hi;
    dst[base + 256] = hi;
    dst[base + 512] = lo;
}

// build split W^T for the concatenated projection weights directly + bias
__global__ void convWcat_kernel(const float* __restrict__ Wt, const float* __restrict__ bt,
                                const float* __restrict__ Wf, const float* __restrict__ bf,
                                const float* __restrict__ Wl, const float* __restrict__ bl,
                                const float* __restrict__ Wp, const float* __restrict__ bp) {
    int i = blockIdx.x * blockDim.x + threadIdx.x;
    if (i < 384 * 256) {
        int n = i >> 8, k = i & 255;
        float v = 0.f;
        if      (n < 64)    v = Wt[k * 64  + n];
        else if (n < 128)   v = Wf[k * 64  + (n - 64)];
        else if (n < 160)   v = Wl[k * 32  + (n - 128)];
        else if (n < PCOLS) v = Wp[k * 128 + (n - 160)];
        __nv_bfloat16 hi = __float2bfloat16(v);
        __nv_bfloat16 lo = __float2bfloat16(v - __bfloat162float(hi));
        size_t base = (size_t)n * K3 + k;
        g_WTQ[base]       = hi;
        g_WTQ[base + 256] = hi;
        g_WTQ[base + 512] = lo;
    }
    if (i < PCOLS) {
        float v;
        if      (i < 64)  v = bt[i];
        else if (i < 128) v = bf[i - 64];
        else if (i < 160) v = bl[i - 128];
        else              v = bp[i - 160];
        g_bcat[i] = v;
    }
}

// ---------------- GEMM tile body: 128x128, BK=32, 4-stage cp.async ----------------
// 8 warps (4M x 2N), warp tile 32x64, m16n8k16 HMMA, fp32 accumulate.
// A stored [M x 512] (hi|lo); chunk source selected per j. B stored [384 x 768].
__device__ __forceinline__ void gemm_body(const __nv_bfloat16* __restrict__ A,
                                          const __nv_bfloat16* __restrict__ Bt,
                                          const float* __restrict__ bias,
                                          float* __restrict__ C,
                                          int N, int rowBase, int colBase, uint32_t sb) {
    const int tid = threadIdx.x, wid = tid >> 5, lane = tid & 31;
    const int wm = wid >> 1, wn = wid & 1;

    auto load = [&](int j, int s) {
        uint32_t abase = sb + s * 16384;
        uint32_t bbase = abase + 8192;
        const __nv_bfloat16* ga = A  + (size_t)rowBase * ASTR + a_chunk_off(j);
        const __nv_bfloat16* gb = Bt + (size_t)colBase * K3 + j * BK;
#pragma unroll
        for (int it = 0; it < 2; it++) {
            int id = tid + it * 256;                // 0..511
            int r = id >> 2, c4 = (id & 3) * 16;
            uint32_t sw = SWZ64(r * 64 + c4);
            cpa16(abase + sw, (const char*)(ga + (size_t)r * ASTR) + c4);
            cpa16(bbase + sw, (const char*)(gb + (size_t)r * K3) + c4);
        }
        CPA_COMMIT();
    };

    float acc[2][8][4];
#pragma unroll
    for (int mi = 0; mi < 2; mi++)
#pragma unroll
        for (int ni = 0; ni < 8; ni++)
#pragma unroll
            for (int q = 0; q < 4; q++) acc[mi][ni][q] = 0.f;

    load(0, 0); load(1, 1); load(2, 2);

    const int aRow = (lane & 15);
    const int aK   = (lane >> 4) << 3;
    const int bRow = (lane & 7) + ((lane >> 4) << 3);
    const int bK   = ((lane >> 3) & 1) << 3;

    for (int i = 0; i < NITER; i++) {
        asm volatile("cp.async.wait_group 2;" ::: "memory");
        __syncthreads();
        if (i + 3 < NITER) load(i + 3, (i + 3) & 3);
        else CPA_COMMIT();                          // keep group accounting uniform

        uint32_t abase = sb + (i & 3) * 16384;
        uint32_t bbase = abase + 8192;
#pragma unroll
        for (int kk = 0; kk < BK; kk += 16) {
            uint32_t a[2][4];
#pragma unroll
            for (int mi = 0; mi < 2; mi++) {
                int row = wm * 32 + mi * 16 + aRow;
                ldsm4(a[mi][0], a[mi][1], a[mi][2], a[mi][3],
                      abase + SWZ64(row * 64 + (kk + aK) * 2));
            }
            uint32_t b[4][4];
#pragma unroll
            for (int ng = 0; ng < 4; ng++) {
                int row = wn * 64 + ng * 16 + bRow;
                ldsm4(b[ng][0], b[ng][1], b[ng][2], b[ng][3],
                      bbase + SWZ64(row * 64 + (kk + bK) * 2));
            }
#pragma unroll
            for (int mi = 0; mi < 2; mi++)
#pragma unroll
                for (int ni = 0; ni < 8; ni++) {
                    int ng = ni >> 1, half = ni & 1;
                    mma16816(acc[mi][ni], a[mi][0], a[mi][1], a[mi][2], a[mi][3],
                             b[ng][half * 2], b[ng][half * 2 + 1]);
                }
        }
    }

    const int g = lane >> 2, tig = lane & 3;
#pragma unroll
    for (int mi = 0; mi < 2; mi++) {
        int r0 = rowBase + wm * 32 + mi * 16 + g;
        int r1 = r0 + 8;
#pragma unroll
        for (int ni = 0; ni < 8; ni++) {
            int c = colBase + wn * 64 + ni * 8 + tig * 2;
            if (c < N) {
                float bx = __ldg(&bias[c]), by = __ldg(&bias[c + 1]);
                float2 v0 = make_float2(acc[mi][ni][0] + bx, acc[mi][ni][1] + by);
                float2 v1 = make_float2(acc[mi][ni][2] + bx, acc[mi][ni][3] + by);
                *reinterpret_cast<float2*>(C + (size_t)r0 * N + c) = v0;
                *reinterpret_cast<float2*>(C + (size_t)r1 * N + c) = v1;
            }
        }
    }
}

// fused value + query GEMM (independent -> one launch to amortize wave tails)
__global__ __launch_bounds__(256, 2)
void gemm_vq(const float* __restrict__ biasV, float* __restrict__ CV,
             float* __restrict__ CQ) {
    extern __shared__ char smem[];                  // 4 * 16384
    uint32_t sb = smem_u32(smem);
    int t = blockIdx.x;
    if (t < VTILES) {
        int rowBase = (t >> 1) * 128, colBase = (t & 1) * 128;
        gemm_body(g_AV, g_WTV, biasV, CV, DM, rowBase, colBase, sb);
    } else {
        t -= VTILES;
        int rowBase = (t / 3) * 128, colBase = (t % 3) * 128;
        gemm_body(g_Abig, g_WTQ, g_bcat, CQ, PCOLS, rowBase, colBase, sb);
    }
}

// single GEMM (output projection)
__global__ __launch_bounds__(256, 2)
void gemm_single(const __nv_bfloat16* __restrict__ A, const __nv_bfloat16* __restrict__ Bt,
                 const float* __restrict__ bias, float* __restrict__ C, int N) {
    extern __shared__ char smem[];
    uint32_t sb = smem_u32(smem);
    int tilesX = (N + 127) / 128;
    int rowBase = (blockIdx.x / tilesX) * 128, colBase = (blockIdx.x % tilesX) * 128;
    gemm_body(A, Bt, bias, C, N, rowBase, colBase, sb);
}

// ---------------- deformable sampling ----------------
__device__ __forceinline__ float tanh_approx(float x) {
    float r;
    asm("tanh.approx.f32 %0, %1;" : "=f"(r) : "f"(x));
    return r;
}

// one warp per (b,q,h). CTA groups 8 consecutive queries of the SAME (b,h) so the
// per-(b,h) level-2/3 working set (~40 KB) stays L1-resident across the block.
// lanes 0..15 precompute the 16 samples' taps; all 32 gather (lane = channel).
__global__ __launch_bounds__(256)
void sample_kernel(const float* __restrict__ refp) {
    __shared__ int   s_idx[8][64];
    __shared__ float s_w[8][64];

    const int warp = threadIdx.x >> 5;
    const int lane = threadIdx.x & 31;
    const int gid = blockIdx.x * 8 + warp;            // h-major: gid = h*32768 + bq
    const int h  = gid >> 15;
    const int bq = gid & 32767;
    const int b  = bq >> 13;                          // NQ=8192

    const float* __restrict__ P = g_P + (size_t)bq * PCOLS;
    const int hL = h * LL;

    if (lane < 16) {
        const int l  = lane >> 2, k = lane & 3;
        const int kt = k >> 1,    kf = k & 1;
        const float t = tanh_approx(P[(hL + l) * 2 + kt]);
        const float f = tanh_approx(P[64 + (hL + l) * 2 + kf]);

        float e0 = P[128 + hL + 0], e1 = P[128 + hL + 1];
        float e2 = P[128 + hL + 2], e3 = P[128 + hL + 3];
        float mx = fmaxf(fmaxf(e0, e1), fmaxf(e2, e3));
        float x0e = __expf(e0 - mx), x1e = __expf(e1 - mx);
        float x2e = __expf(e2 - mx), x3e = __expf(e3 - mx);
        float lsum = x0e + x1e + x2e + x3e;
        float lwv = (l == 0 ? x0e : l == 1 ? x1e : l == 2 ? x2e : x3e);

        const float* pp = P + 160 + (hL + l) * 4;
        float p0 = pp[0], p1 = pp[1], p2 = pp[2], p3 = pp[3];
        float pm = fmaxf(fmaxf(p0, p1), fmaxf(p2, p3));
        float q0 = __expf(p0 - pm), q1 = __expf(p1 - pm);
        float q2 = __expf(p2 - pm), q3 = __expf(p3 - pm);
        float psum = q0 + q1 + q2 + q3;
        float pwv = (k == 0 ? q0 : k == 1 ? q1 : k == 2 ? q2 : q3);

        const float a = __fdividef(lwv * pwv, lsum * psum);

        const float* rp = refp + (size_t)bq * (LL * 2);
        const int   Wl = c_Wl[l];
        const int   start = c_lsi[l];
        const float fWl = (float)Wl;
        float lx = rp[l * 2 + 0] + t * c_inv[l];
        float ly = rp[l * 2 + 1] + f * c_inv[l];
        lx = fminf(fmaxf(lx, 0.f), 1.f);
        ly = fminf(fmaxf(ly, 0.f), 1.f);
        float x = lx * fWl - 0.5f;
        float y = ly * fWl - 0.5f;       // Hl == Wl for all levels
        float x0f = floorf(x), y0f = floorf(y);
        float wx1 = x - x0f, wy1 = y - y0f;
        float wx0 = 1.f - wx1, wy0 = 1.f - wy1;
        int x0 = (int)x0f, y0 = (int)y0f;

#pragma unroll
        for (int j = 0; j < 4; j++) {
            int xi = x0 + (j & 1), yi = y0 + (j >> 1);
            float w = a * ((j & 1) ? wx1 : wx0) * ((j >> 1) ? wy1 : wy0);
            bool valid = (xi >= 0) & (xi < Wl) & (yi >= 0) & (yi < Wl);
            int xc = min(max(xi, 0), Wl - 1);
            int yc = min(max(yi, 0), Wl - 1);
            s_idx[warp][lane * 4 + j] = start + yc * Wl + xc;
            s_w[warp][lane * 4 + j]   = valid ? w : 0.f;
        }
    }
    __syncwarp();

    const float* __restrict__ vb = g_v + (size_t)b * NVV * DM + h * DHD + lane;
    float acc = 0.f;
#pragma unroll 16
    for (int t = 0; t < 64; t++) {
        acc += s_w[warp][t] * vb[(size_t)s_idx[warp][t] * DM];
    }

    // write directly as split-bf16 into Abig for the output GEMM
    const int col = h * DHD + lane;
    size_t base = (size_t)bq * ASTR + col;
    __nv_bfloat16 hi = __float2bfloat16(acc);
    __nv_bfloat16 lo = __float2bfloat16(acc - __bfloat162float(hi));
    g_Abig[base]       = hi;
    g_Abig[base + 256] = lo;
}

// ---------------- launch ----------------
extern "C" void kernel_launch(void* const* d_in, const int* in_sizes, int n_in,
                              void* d_out, int out_size) {
    const float* query  = (const float*)d_in[0];
    const float* refp   = (const float*)d_in[1];
    const float* value  = (const float*)d_in[2];
    const float* W_time = (const float*)d_in[5];
    const float* b_time = (const float*)d_in[6];
    const float* W_freq = (const float*)d_in[7];
    const float* b_freq = (const float*)d_in[8];
    const float* W_lvl  = (const float*)d_in[9];
    const float* b_lvl  = (const float*)d_in[10];
    const float* W_pt   = (const float*)d_in[11];
    const float* b_pt   = (const float*)d_in[12];
    const float* W_v    = (const float*)d_in[13];
    const float* b_v    = (const float*)d_in[14];
    const float* W_o    = (const float*)d_in[15];
    const float* b_o    = (const float*)d_in[16];
    float* out = (float*)d_out;

    float *p_v, *p_P;
    __nv_bfloat16 *p_Abig, *p_AV, *p_WTV;
    cudaGetSymbolAddress((void**)&p_v,    g_v);
    cudaGetSymbolAddress((void**)&p_P,    g_P);
    cudaGetSymbolAddress((void**)&p_Abig, g_Abig);
    cudaGetSymbolAddress((void**)&p_AV,   g_AV);
    cudaGetSymbolAddress((void**)&p_WTV,  g_WTV);

    const int GEMM_SMEM = 4 * 16384;   // 64 KB
    cudaFuncSetAttribute(gemm_vq,     cudaFuncAttributeMaxDynamicSharedMemorySize, GEMM_SMEM);
    cudaFuncSetAttribute(gemm_single, cudaFuncAttributeMaxDynamicSharedMemorySize, GEMM_SMEM);

    // 1) weight conversions + A conversions (all independent)
    convW_kernel<<<(384 * 256 + 255) / 256, 256>>>(W_v, p_WTV, DM);
    convWcat_kernel<<<(384 * 256 + 255) / 256, 256>>>(W_time, b_time, W_freq, b_freq,
                                                      W_lvl, b_lvl, W_pt, b_pt);
    convA_kernel<<<(BB * NVV * DM + 255) / 256, 256>>>(value, p_AV, BB * NVV * DM);
    convA_kernel<<<(BB * NQ * DM + 255) / 256, 256>>>(query, p_Abig, BB * NQ * DM);

    // 2) fused value + query GEMMs (340 + 768 = 1108 CTAs)
    gemm_vq<<<VTILES + 768, 256, GEMM_SMEM>>>(b_v, p_v, p_P);

    // 3) deformable sampling (L1-blocked by (b,h)) -> split-bf16 mid into Abig
    sample_kernel<<<(BB * NQ * HH) / 8, 256>>>(refp);

    // 4) output GEMM: out = mid @ W_o + b_o   [32768 x 256]
    convW_kernel<<<(384 * 256 + 255) / 256, 256>>>(W_o, p_WTV, DM);
    gemm_single<<<512, 256, GEMM_SMEM>>>(p_Abig, p_WTV, b_o, out, DM);
}

// round 10
// speedup vs baseline: 1.5691x; 1.0146x over previous
#include <cuda_runtime.h>
#include <cuda_bf16.h>
#include <cuda_fp16.h>
#include <cstdint>

// ---------------- problem constants ----------------
#define BB   4
#define NQ   8192
#define DM   256
#define HH   8
#define LL   4
#define DHD  32
#define NVV  5440
#define PCOLS 288
#define K3   768          // logical split-K: [A_hi | A_lo | A_hi] x [W_hi ; W_hi ; W_lo]
#define ASTR 512          // physical A storage: [A_hi | A_lo], 512 cols
#define NITER 24          // 768 / 32
#define BK   32
#define VTILES 340        // value GEMM: 170 row-tiles x 2 col-tiles

// conv_all block ranges (each block handles 256 elements)
#define CB_QA 32768                    // query convA: 32768*256 = 8388608 elems
#define CB_VA (CB_QA + 21760)          // value convA: 21760*256 = 5570560 elems
#define CB_WV (CB_VA + 384)            // W_v
#define CB_WO (CB_WV + 384)            // W_o
#define CB_WQ (CB_WO + 384)            // Wcat (+ bias)

__device__ __constant__ int   c_Wl[LL]   = {64, 32, 16, 8};
__device__ __constant__ int   c_lsi[LL]  = {0, 4096, 5120, 5376};
__device__ __constant__ float c_inv[LL]  = {1.f/64.f, 1.f/32.f, 1.f/16.f, 1.f/8.f};

// ---------------- static device scratch ----------------
__device__ __nv_bfloat16 g_Abig[32768 * ASTR];  // split-bf16 A (query, then mid)
__device__ __nv_bfloat16 g_AV[BB * NVV * ASTR]; // split-bf16 A (value)
__device__ __nv_bfloat16 g_WTV[384 * K3];       // split W^T for W_v
__device__ __nv_bfloat16 g_WTO[384 * K3];       // split W^T for W_o
__device__ __nv_bfloat16 g_WTQ[384 * K3];       // split W^T for Wcat
__device__ __half g_v[BB * NVV * DM];           // projected value, fp16
__device__ float g_P[BB * NQ * PCOLS];
__device__ float g_bcat[PCOLS];

// ---------------- helpers ----------------
__device__ __forceinline__ uint32_t smem_u32(const void* p) {
    uint32_t a;
    asm("{ .reg .u64 t; cvta.to.shared.u64 t, %1; cvt.u32.u64 %0, t; }" : "=r"(a) : "l"(p));
    return a;
}
__device__ __forceinline__ void cpa16(uint32_t s, const void* g) {
    asm volatile("cp.async.cg.shared.global [%0], [%1], 16;" :: "r"(s), "l"(g));
}
#define CPA_COMMIT() asm volatile("cp.async.commit_group;" ::: "memory")
#define SWZ64(x) ((x) ^ (((x) >> 3) & 0x30))

__device__ __forceinline__ void ldsm4(uint32_t& r0, uint32_t& r1, uint32_t& r2, uint32_t& r3,
                                      uint32_t addr) {
    asm volatile("ldmatrix.sync.aligned.m8n8.x4.shared.b16 {%0,%1,%2,%3}, [%4];"
                 : "=r"(r0), "=r"(r1), "=r"(r2), "=r"(r3) : "r"(addr));
}
__device__ __forceinline__ void mma16816(float* c, uint32_t a0, uint32_t a1, uint32_t a2,
                                         uint32_t a3, uint32_t b0, uint32_t b1) {
    asm volatile("mma.sync.aligned.m16n8k16.row.col.f32.bf16.bf16.f32 "
                 "{%0,%1,%2,%3}, {%4,%5,%6,%7}, {%8,%9}, {%0,%1,%2,%3};"
                 : "+f"(c[0]), "+f"(c[1]), "+f"(c[2]), "+f"(c[3])
                 : "r"(a0), "r"(a1), "r"(a2), "r"(a3), "r"(b0), "r"(b1));
}

// chunk j (0..23) -> element offset inside the 512-col A storage
__device__ __forceinline__ int a_chunk_off(int j) {
    int jj = (j < 16) ? j : (j - 16);
    return ((jj & 8) ? 256 : 0) + (jj & 7) * BK;
}

// ---------------- one-launch conversions ----------------
__device__ __forceinline__ void splitA_elem(const float* A, __nv_bfloat16* dst, int i) {
    int r = i >> 8, c = i & 255;
    float v = A[i];
    __nv_bfloat16 hi = __float2bfloat16(v);
    __nv_bfloat16 lo = __float2bfloat16(v - __bfloat162float(hi));
    size_t base = (size_t)r * ASTR + c;
    dst[base]       = hi;
    dst[base + 256] = lo;
}
__device__ __forceinline__ void splitW_elem(const float* W, __nv_bfloat16* dst, int N, int i) {
    int n = i >> 8, k = i & 255;
    float v = (n < N) ? W[k * N + n] : 0.f;
    __nv_bfloat16 hi = __float2bfloat16(v);
    __nv_bfloat16 lo = __float2bfloat16(v - __bfloat162float(hi));
    size_t base = (size_t)n * K3 + k;
    dst[base]       = hi;
    dst[base + 256] = hi;
    dst[base + 512] = lo;
}

__global__ void conv_all(const float* __restrict__ query, const float* __restrict__ value,
                         const float* __restrict__ Wv, const float* __restrict__ Wo,
                         const float* __restrict__ Wt, const float* __restrict__ bt,
                         const float* __restrict__ Wf, const float* __restrict__ bf,
                         const float* __restrict__ Wl, const float* __restrict__ bl,
                         const float* __restrict__ Wp, const float* __restrict__ bp) {
    int blk = blockIdx.x;
    int tid = threadIdx.x;
    if (blk < CB_QA) {
        splitA_elem(query, g_Abig, blk * 256 + tid);
    } else if (blk < CB_VA) {
        splitA_elem(value, g_AV, (blk - CB_QA) * 256 + tid);
    } else if (blk < CB_WV) {
        splitW_elem(Wv, g_WTV, DM, (blk - CB_VA) * 256 + tid);
    } else if (blk < CB_WO) {
        splitW_elem(Wo, g_WTO, DM, (blk - CB_WV) * 256 + tid);
    } else {
        int i = (blk - CB_WO) * 256 + tid;
        int n = i >> 8, k = i & 255;
        float v = 0.f;
        if      (n < 64)    v = Wt[k * 64  + n];
        else if (n < 128)   v = Wf[k * 64  + (n - 64)];
        else if (n < 160)   v = Wl[k * 32  + (n - 128)];
        else if (n < PCOLS) v = Wp[k * 128 + (n - 160)];
        __nv_bfloat16 hi = __float2bfloat16(v);
        __nv_bfloat16 lo = __float2bfloat16(v - __bfloat162float(hi));
        size_t base = (size_t)n * K3 + k;
        g_WTQ[base]       = hi;
        g_WTQ[base + 256] = hi;
        g_WTQ[base + 512] = lo;
        if (i < PCOLS) {
            float bv;
            if      (i < 64)  bv = bt[i];
            else if (i < 128) bv = bf[i - 64];
            else if (i < 160) bv = bl[i - 128];
            else              bv = bp[i - 160];
            g_bcat[i] = bv;
        }
    }
}

// ---------------- GEMM tile body: 128x128, BK=32, 4-stage cp.async ----------------
// 8 warps (4M x 2N), warp tile 32x64, m16n8k16 HMMA, fp32 accumulate.
// A stored [M x 512] (hi|lo); chunk source selected per j. B stored [384 x 768].
template <bool HALF_OUT>
__device__ __forceinline__ void gemm_body(const __nv_bfloat16* __restrict__ A,
                                          const __nv_bfloat16* __restrict__ Bt,
                                          const float* __restrict__ bias,
                                          void* __restrict__ Cv,
                                          int N, int rowBase, int colBase, uint32_t sb) {
    const int tid = threadIdx.x, wid = tid >> 5, lane = tid & 31;
    const int wm = wid >> 1, wn = wid & 1;

    auto load = [&](int j, int s) {
        uint32_t abase = sb + s * 16384;
        uint32_t bbase = abase + 8192;
        const __nv_bfloat16* ga = A  + (size_t)rowBase * ASTR + a_chunk_off(j);
        const __nv_bfloat16* gb = Bt + (size_t)colBase * K3 + j * BK;
#pragma unroll
        for (int it = 0; it < 2; it++) {
            int id = tid + it * 256;                // 0..511
            int r = id >> 2, c4 = (id & 3) * 16;
            uint32_t sw = SWZ64(r * 64 + c4);
            cpa16(abase + sw, (const char*)(ga + (size_t)r * ASTR) + c4);
            cpa16(bbase + sw, (const char*)(gb + (size_t)r * K3) + c4);
        }
        CPA_COMMIT();
    };

    float acc[2][8][4];
#pragma unroll
    for (int mi = 0; mi < 2; mi++)
#pragma unroll
        for (int ni = 0; ni < 8; ni++)
#pragma unroll
            for (int q = 0; q < 4; q++) acc[mi][ni][q] = 0.f;

    load(0, 0); load(1, 1); load(2, 2);

    const int aRow = (lane & 15);
    const int aK   = (lane >> 4) << 3;
    const int bRow = (lane & 7) + ((lane >> 4) << 3);
    const int bK   = ((lane >> 3) & 1) << 3;

    for (int i = 0; i < NITER; i++) {
        asm volatile("cp.async.wait_group 2;" ::: "memory");
        __syncthreads();
        if (i + 3 < NITER) load(i + 3, (i + 3) & 3);
        else CPA_COMMIT();                          // keep group accounting uniform

        uint32_t abase = sb + (i & 3) * 16384;
        uint32_t bbase = abase + 8192;
#pragma unroll
        for (int kk = 0; kk < BK; kk += 16) {
            uint32_t a[2][4];
#pragma unroll
            for (int mi = 0; mi < 2; mi++) {
                int row = wm * 32 + mi * 16 + aRow;
                ldsm4(a[mi][0], a[mi][1], a[mi][2], a[mi][3],
                      abase + SWZ64(row * 64 + (kk + aK) * 2));
            }
            uint32_t b[4][4];
#pragma unroll
            for (int ng = 0; ng < 4; ng++) {
                int row = wn * 64 + ng * 16 + bRow;
                ldsm4(b[ng][0], b[ng][1], b[ng][2], b[ng][3],
                      bbase + SWZ64(row * 64 + (kk + bK) * 2));
            }
#pragma unroll
            for (int mi = 0; mi < 2; mi++)
#pragma unroll
                for (int ni = 0; ni < 8; ni++) {
                    int ng = ni >> 1, half = ni & 1;
                    mma16816(acc[mi][ni], a[mi][0], a[mi][1], a[mi][2], a[mi][3],
                             b[ng][half * 2], b[ng][half * 2 + 1]);
                }
        }
    }

    const int g = lane >> 2, tig = lane & 3;
#pragma unroll
    for (int mi = 0; mi < 2; mi++) {
        int r0 = rowBase + wm * 32 + mi * 16 + g;
        int r1 = r0 + 8;
#pragma unroll
        for (int ni = 0; ni < 8; ni++) {
            int c = colBase + wn * 64 + ni * 8 + tig * 2;
            if (c < N) {
                float bx = __ldg(&bias[c]), by = __ldg(&bias[c + 1]);
                if (HALF_OUT) {
                    __half* C = (__half*)Cv;
                    *reinterpret_cast<__half2*>(C + (size_t)r0 * N + c) =
                        __floats2half2_rn(acc[mi][ni][0] + bx, acc[mi][ni][1] + by);
                    *reinterpret_cast<__half2*>(C + (size_t)r1 * N + c) =
                        __floats2half2_rn(acc[mi][ni][2] + bx, acc[mi][ni][3] + by);
                } else {
                    float* C = (float*)Cv;
                    float2 v0 = make_float2(acc[mi][ni][0] + bx, acc[mi][ni][1] + by);
                    float2 v1 = make_float2(acc[mi][ni][2] + bx, acc[mi][ni][3] + by);
                    *reinterpret_cast<float2*>(C + (size_t)r0 * N + c) = v0;
                    *reinterpret_cast<float2*>(C + (size_t)r1 * N + c) = v1;
                }
            }
        }
    }
}

// fused value + query GEMM (independent -> one launch to amortize wave tails)
__global__ __launch_bounds__(256, 2)
void gemm_vq(const float* __restrict__ biasV, float* __restrict__ CQ) {
    extern __shared__ char smem[];                  // 4 * 16384
    uint32_t sb = smem_u32(smem);
    int t = blockIdx.x;
    if (t < VTILES) {
        int rowBase = (t >> 1) * 128, colBase = (t & 1) * 128;
        gemm_body<true>(g_AV, g_WTV, biasV, g_v, DM, rowBase, colBase, sb);
    } else {
        t -= VTILES;
        int rowBase = (t / 3) * 128, colBase = (t % 3) * 128;
        gemm_body<false>(g_Abig, g_WTQ, g_bcat, CQ, PCOLS, rowBase, colBase, sb);
    }
}

// single GEMM (output projection)
__global__ __launch_bounds__(256, 2)
void gemm_single(const __nv_bfloat16* __restrict__ A, const __nv_bfloat16* __restrict__ Bt,
                 const float* __restrict__ bias, float* __restrict__ C, int N) {
    extern __shared__ char smem[];
    uint32_t sb = smem_u32(smem);
    int tilesX = (N + 127) / 128;
    int rowBase = (blockIdx.x / tilesX) * 128, colBase = (blockIdx.x % tilesX) * 128;
    gemm_body<false>(A, Bt, bias, C, N, rowBase, colBase, sb);
}

// ---------------- deformable sampling ----------------
__device__ __forceinline__ float tanh_approx(float x) {
    float r;
    asm("tanh.approx.f32 %0, %1;" : "=f"(r) : "f"(x));
    return r;
}

// one warp per (b,q,h), h-major grouping for L1 locality on small levels.
// lanes 0..15 precompute the 16 samples' taps; all 32 gather (lane = channel).
// v is fp16 -> 64 B per tap-warp (halved L2 traffic).
__global__ __launch_bounds__(256)
void sample_kernel(const float* __restrict__ refp) {
    __shared__ int   s_idx[8][64];
    __shared__ float s_w[8][64];

    const int warp = threadIdx.x >> 5;
    const int lane = threadIdx.x & 31;
    const int gid = blockIdx.x * 8 + warp;            // h-major: gid = h*32768 + bq
    const int h  = gid >> 15;
    const int bq = gid & 32767;
    const int b  = bq >> 13;                          // NQ=8192

    const float* __restrict__ P = g_P + (size_t)bq * PCOLS;
    const int hL = h * LL;

    if (lane < 16) {
        const int l  = lane >> 2, k = lane & 3;
        const int kt = k >> 1,    kf = k & 1;
        const float t = tanh_approx(P[(hL + l) * 2 + kt]);
        const float f = tanh_approx(P[64 + (hL + l) * 2 + kf]);

        float e0 = P[128 + hL + 0], e1 = P[128 + hL + 1];
        float e2 = P[128 + hL + 2], e3 = P[128 + hL + 3];
        float mx = fmaxf(fmaxf(e0, e1), fmaxf(e2, e3));
        float x0e = __expf(e0 - mx), x1e = __expf(e1 - mx);
        float x2e = __expf(e2 - mx), x3e = __expf(e3 - mx);
        float lsum = x0e + x1e + x2e + x3e;
        float lwv = (l == 0 ? x0e : l == 1 ? x1e : l == 2 ? x2e : x3e);

        const float* pp = P + 160 + (hL + l) * 4;
        float p0 = pp[0], p1 = pp[1], p2 = pp[2], p3 = pp[3];
        float pm = fmaxf(fmaxf(p0, p1), fmaxf(p2, p3));
        float q0 = __expf(p0 - pm), q1 = __expf(p1 - pm);
        float q2 = __expf(p2 - pm), q3 = __expf(p3 - pm);
        float psum = q0 + q1 + q2 + q3;
        float pwv = (k == 0 ? q0 : k == 1 ? q1 : k == 2 ? q2 : q3);

        const float a = __fdividef(lwv * pwv, lsum * psum);

        const float* rp = refp + (size_t)bq * (LL * 2);
        const int   Wl = c_Wl[l];
        const int   start = c_lsi[l];
        const float fWl = (float)Wl;
        float lx = rp[l * 2 + 0] + t * c_inv[l];
        float ly = rp[l * 2 + 1] + f * c_inv[l];
        lx = fminf(fmaxf(lx, 0.f), 1.f);
        ly = fminf(fmaxf(ly, 0.f), 1.f);
        float x = lx * fWl - 0.5f;
        float y = ly * fWl - 0.5f;       // Hl == Wl for all levels
        float x0f = floorf(x), y0f = floorf(y);
        float wx1 = x - x0f, wy1 = y - y0f;
        float wx0 = 1.f - wx1, wy0 = 1.f - wy1;
        int x0 = (int)x0f, y0 = (int)y0f;

#pragma unroll
        for (int j = 0; j < 4; j++) {
            int xi = x0 + (j & 1), yi = y0 + (j >> 1);
            float w = a * ((j & 1) ? wx1 : wx0) * ((j >> 1) ? wy1 : wy0);
            bool valid = (xi >= 0) & (xi < Wl) & (yi >= 0) & (yi < Wl);
            int xc = min(max(xi, 0), Wl - 1);
            int yc = min(max(yi, 0), Wl - 1);
            s_idx[warp][lane * 4 + j] = start + yc * Wl + xc;
            s_w[warp][lane * 4 + j]   = valid ? w : 0.f;
        }
    }
    __syncwarp();

    const __half* __restrict__ vb = g_v + (size_t)b * NVV * DM + h * DHD + lane;
    float acc = 0.f;
#pragma unroll 16
    for (int t = 0; t < 64; t++) {
        acc += s_w[warp][t] * __half2float(vb[(size_t)s_idx[warp][t] * DM]);
    }

    // write directly as split-bf16 into Abig for the output GEMM
    const int col = h * DHD + lane;
    size_t base = (size_t)bq * ASTR + col;
    __nv_bfloat16 hi = __float2bfloat16(acc);
    __nv_bfloat16 lo = __float2bfloat16(acc - __bfloat162float(hi));
    g_Abig[base]       = hi;
    g_Abig[base + 256] = lo;
}

// ---------------- launch ----------------
extern "C" void kernel_launch(void* const* d_in, const int* in_sizes, int n_in,
                              void* d_out, int out_size) {
    const float* query  = (const float*)d_in[0];
    const float* refp   = (const float*)d_in[1];
    const float* value  = (const float*)d_in[2];
    const float* W_time = (const float*)d_in[5];
    const float* b_time = (const float*)d_in[6];
    const float* W_freq = (const float*)d_in[7];
    const float* b_freq = (const float*)d_in[8];
    const float* W_lvl  = (const float*)d_in[9];
    const float* b_lvl  = (const float*)d_in[10];
    const float* W_pt   = (const float*)d_in[11];
    const float* b_pt   = (const float*)d_in[12];
    const float* W_v    = (const float*)d_in[13];
    const float* b_v    = (const float*)d_in[14];
    const float* W_o    = (const float*)d_in[15];
    const float* b_o    = (const float*)d_in[16];
    float* out = (float*)d_out;

    float *p_P;
    __nv_bfloat16 *p_Abig, *p_WTO;
    cudaGetSymbolAddress((void**)&p_P,    g_P);
    cudaGetSymbolAddress((void**)&p_Abig, g_Abig);
    cudaGetSymbolAddress((void**)&p_WTO,  g_WTO);

    const int GEMM_SMEM = 4 * 16384;   // 64 KB
    cudaFuncSetAttribute(gemm_vq,     cudaFuncAttributeMaxDynamicSharedMemorySize, GEMM_SMEM);
    cudaFuncSetAttribute(gemm_single, cudaFuncAttributeMaxDynamicSharedMemorySize, GEMM_SMEM);

    // 1) all conversions in ONE launch
    conv_all<<<CB_WQ, 256>>>(query, value, W_v, W_o,
                             W_time, b_time, W_freq, b_freq,
                             W_lvl, b_lvl, W_pt, b_pt);

    // 2) fused value + query GEMMs (340 + 768 = 1108 CTAs); value out = fp16 g_v
    gemm_vq<<<VTILES + 768, 256, GEMM_SMEM>>>(b_v, p_P);

    // 3) deformable sampling (fp16 v gather) -> split-bf16 mid into Abig
    sample_kernel<<<(BB * NQ * HH) / 8, 256>>>(refp);

    // 4) output GEMM: out = mid @ W_o + b_o   [32768 x 256]
    gemm_single<<<512, 256, GEMM_SMEM>>>(p_Abig, p_WTO, b_o, out, DM);
}

// round 11
// speedup vs baseline: 2.0138x; 1.2834x over previous
#include <cuda_runtime.h>
#include <cuda_bf16.h>
#include <cuda_fp16.h>
#include <cstdint>

// ---------------- problem constants ----------------
#define BB   4
#define NQ   8192
#define DM   256
#define HH   8
#define LL   4
#define DHD  32
#define NVV  5440
#define PCOLS 288
#define K3   768          // logical split-K: [A_hi | A_lo | A_hi] x [W_hi ; W_hi ; W_lo]
#define ASTR 512          // physical A storage: [A_hi | A_lo], 512 cols
#define NITER 24          // 768 / 32
#define BK   32
#define VTILES 340        // value GEMM: 170 row-tiles x 2 col-tiles

// conv_all block ranges (each block handles 1024 elements, 4 per thread)
#define CB_QA 8192                     // query convA: 8192*1024 = 8388608 elems
#define CB_VA (CB_QA + 5440)           // value convA: 5440*1024 = 5570560 elems
#define CB_WV (CB_VA + 96)             // W_v:   98304 elems
#define CB_WO (CB_WV + 96)             // W_o
#define CB_WQ (CB_WO + 96)             // Wcat (+ bias)

__device__ __constant__ int   c_Wl[LL]   = {64, 32, 16, 8};
__device__ __constant__ int   c_lsi[LL]  = {0, 4096, 5120, 5376};
__device__ __constant__ float c_inv[LL]  = {1.f/64.f, 1.f/32.f, 1.f/16.f, 1.f/8.f};

// ---------------- static device scratch ----------------
__device__ __nv_bfloat16 g_Abig[32768 * ASTR];  // split-bf16 A (query, then mid)
__device__ __nv_bfloat16 g_AV[BB * NVV * ASTR]; // split-bf16 A (value)
__device__ __nv_bfloat16 g_WTV[384 * K3];       // split W^T for W_v
__device__ __nv_bfloat16 g_WTO[384 * K3];       // split W^T for W_o
__device__ __nv_bfloat16 g_WTQ[384 * K3];       // split W^T for Wcat
__device__ __half g_v[BB * NVV * DM];           // projected value, fp16
__device__ float g_P[BB * NQ * PCOLS];
__device__ float g_bcat[PCOLS];

// ---------------- helpers ----------------
__device__ __forceinline__ uint32_t smem_u32(const void* p) {
    uint32_t a;
    asm("{ .reg .u64 t; cvta.to.shared.u64 t, %1; cvt.u32.u64 %0, t; }" : "=r"(a) : "l"(p));
    return a;
}
__device__ __forceinline__ void cpa16(uint32_t s, const void* g) {
    asm volatile("cp.async.cg.shared.global [%0], [%1], 16;" :: "r"(s), "l"(g));
}
#define CPA_COMMIT() asm volatile("cp.async.commit_group;" ::: "memory")
#define SWZ64(x) ((x) ^ (((x) >> 3) & 0x30))

__device__ __forceinline__ void ldsm4(uint32_t& r0, uint32_t& r1, uint32_t& r2, uint32_t& r3,
                                      uint32_t addr) {
    asm volatile("ldmatrix.sync.aligned.m8n8.x4.shared.b16 {%0,%1,%2,%3}, [%4];"
                 : "=r"(r0), "=r"(r1), "=r"(r2), "=r"(r3) : "r"(addr));
}
__device__ __forceinline__ void mma16816(float* c, uint32_t a0, uint32_t a1, uint32_t a2,
                                         uint32_t a3, uint32_t b0, uint32_t b1) {
    asm volatile("mma.sync.aligned.m16n8k16.row.col.f32.bf16.bf16.f32 "
                 "{%0,%1,%2,%3}, {%4,%5,%6,%7}, {%8,%9}, {%0,%1,%2,%3};"
                 : "+f"(c[0]), "+f"(c[1]), "+f"(c[2]), "+f"(c[3])
                 : "r"(a0), "r"(a1), "r"(a2), "r"(a3), "r"(b0), "r"(b1));
}

// chunk j (0..23) -> element offset inside the 512-col A storage
__device__ __forceinline__ int a_chunk_off(int j) {
    int jj = (j < 16) ? j : (j - 16);
    return ((jj & 8) ? 256 : 0) + (jj & 7) * BK;
}

// ---------------- one-launch vectorized conversions ----------------
__device__ __forceinline__ uint32_t pack_bf2(float a, float b) {
    uint32_t r;
    asm("cvt.rn.bf16x2.f32 %0, %2, %1;" : "=r"(r) : "f"(a), "f"(b));   // lo=a, hi=b
    return r;
}
__device__ __forceinline__ void splitA4(const float* __restrict__ A,
                                        __nv_bfloat16* __restrict__ dst, int i4) {
    int base = i4 * 4;
    int r = base >> 8, c = base & 255;
    float4 v = *reinterpret_cast<const float4*>(A + base);
    float hx = __bfloat162float(__float2bfloat16(v.x));
    float hy = __bfloat162float(__float2bfloat16(v.y));
    float hz = __bfloat162float(__float2bfloat16(v.z));
    float hw = __bfloat162float(__float2bfloat16(v.w));
    uint2 hi = make_uint2(pack_bf2(hx, hy), pack_bf2(hz, hw));
    uint2 lo = make_uint2(pack_bf2(v.x - hx, v.y - hy), pack_bf2(v.z - hz, v.w - hw));
    __nv_bfloat16* p = dst + (size_t)r * ASTR + c;
    *reinterpret_cast<uint2*>(p)       = hi;
    *reinterpret_cast<uint2*>(p + 256) = lo;
}
__device__ __forceinline__ void splitW4(const float* __restrict__ W,
                                        __nv_bfloat16* __restrict__ dst, int N, int i4) {
    int base = i4 * 4;
    int n = base >> 8, k = base & 255;        // 4 consecutive k, same n
    float v0 = (n < N) ? W[(k + 0) * N + n] : 0.f;
    float v1 = (n < N) ? W[(k + 1) * N + n] : 0.f;
    float v2 = (n < N) ? W[(k + 2) * N + n] : 0.f;
    float v3 = (n < N) ? W[(k + 3) * N + n] : 0.f;
    float h0 = __bfloat162float(__float2bfloat16(v0));
    float h1 = __bfloat162float(__float2bfloat16(v1));
    float h2 = __bfloat162float(__float2bfloat16(v2));
    float h3 = __bfloat162float(__float2bfloat16(v3));
    uint2 hi = make_uint2(pack_bf2(h0, h1), pack_bf2(h2, h3));
    uint2 lo = make_uint2(pack_bf2(v0 - h0, v1 - h1), pack_bf2(v2 - h2, v3 - h3));
    __nv_bfloat16* p = dst + (size_t)n * K3 + k;
    *reinterpret_cast<uint2*>(p)       = hi;
    *reinterpret_cast<uint2*>(p + 256) = hi;
    *reinterpret_cast<uint2*>(p + 512) = lo;
}

__global__ void conv_all(const float* __restrict__ query, const float* __restrict__ value,
                         const float* __restrict__ Wv, const float* __restrict__ Wo,
                         const float* __restrict__ Wt, const float* __restrict__ bt,
                         const float* __restrict__ Wf, const float* __restrict__ bf,
                         const float* __restrict__ Wl, const float* __restrict__ bl,
                         const float* __restrict__ Wp, const float* __restrict__ bp) {
    int blk = blockIdx.x;
    int tid = threadIdx.x;
    if (blk < CB_QA) {
        splitA4(query, g_Abig, blk * 256 + tid);
    } else if (blk < CB_VA) {
        splitA4(value, g_AV, (blk - CB_QA) * 256 + tid);
    } else if (blk < CB_WV) {
        splitW4(Wv, g_WTV, DM, (blk - CB_VA) * 256 + tid);
    } else if (blk < CB_WO) {
        splitW4(Wo, g_WTO, DM, (blk - CB_WV) * 256 + tid);
    } else {
        int i4 = (blk - CB_WO) * 256 + tid;
        int base = i4 * 4;
        int n = base >> 8, k = base & 255;
        float v[4];
#pragma unroll
        for (int j = 0; j < 4; j++) {
            int kk = k + j;
            float x = 0.f;
            if      (n < 64)    x = Wt[kk * 64  + n];
            else if (n < 128)   x = Wf[kk * 64  + (n - 64)];
            else if (n < 160)   x = Wl[kk * 32  + (n - 128)];
            else if (n < PCOLS) x = Wp[kk * 128 + (n - 160)];
            v[j] = x;
        }
        float h0 = __bfloat162float(__float2bfloat16(v[0]));
        float h1 = __bfloat162float(__float2bfloat16(v[1]));
        float h2 = __bfloat162float(__float2bfloat16(v[2]));
        float h3 = __bfloat162float(__float2bfloat16(v[3]));
        uint2 hi = make_uint2(pack_bf2(h0, h1), pack_bf2(h2, h3));
        uint2 lo = make_uint2(pack_bf2(v[0] - h0, v[1] - h1), pack_bf2(v[2] - h2, v[3] - h3));
        __nv_bfloat16* p = g_WTQ + (size_t)n * K3 + k;
        *reinterpret_cast<uint2*>(p)       = hi;
        *reinterpret_cast<uint2*>(p + 256) = hi;
        *reinterpret_cast<uint2*>(p + 512) = lo;
        // bias (first 288 global elements, one elem per thread covering 4)
        if (i4 < (PCOLS + 3) / 4 * 1) { /* handled below instead */ }
        if (base < PCOLS) {
#pragma unroll
            for (int j = 0; j < 4; j++) {
                int i = base + j;
                if (i < PCOLS) {
                    float bv;
                    if      (i < 64)  bv = bt[i];
                    else if (i < 128) bv = bf[i - 64];
                    else if (i < 160) bv = bl[i - 128];
                    else              bv = bp[i - 160];
                    g_bcat[i] = bv;
                }
            }
        }
    }
}

// ---------------- GEMM tile body: 128x128, BK=32, 4-stage cp.async ----------------
template <bool HALF_OUT>
__device__ __forceinline__ void gemm_body(const __nv_bfloat16* __restrict__ A,
                                          const __nv_bfloat16* __restrict__ Bt,
                                          const float* __restrict__ bias,
                                          void* __restrict__ Cv,
                                          int N, int rowBase, int colBase, uint32_t sb) {
    const int tid = threadIdx.x, wid = tid >> 5, lane = tid & 31;
    const int wm = wid >> 1, wn = wid & 1;

    auto load = [&](int j, int s) {
        uint32_t abase = sb + s * 16384;
        uint32_t bbase = abase + 8192;
        const __nv_bfloat16* ga = A  + (size_t)rowBase * ASTR + a_chunk_off(j);
        const __nv_bfloat16* gb = Bt + (size_t)colBase * K3 + j * BK;
#pragma unroll
        for (int it = 0; it < 2; it++) {
            int id = tid + it * 256;                // 0..511
            int r = id >> 2, c4 = (id & 3) * 16;
            uint32_t sw = SWZ64(r * 64 + c4);
            cpa16(abase + sw, (const char*)(ga + (size_t)r * ASTR) + c4);
            cpa16(bbase + sw, (const char*)(gb + (size_t)r * K3) + c4);
        }
        CPA_COMMIT();
    };

    float acc[2][8][4];
#pragma unroll
    for (int mi = 0; mi < 2; mi++)
#pragma unroll
        for (int ni = 0; ni < 8; ni++)
#pragma unroll
            for (int q = 0; q < 4; q++) acc[mi][ni][q] = 0.f;

    load(0, 0); load(1, 1); load(2, 2);

    const int aRow = (lane & 15);
    const int aK   = (lane >> 4) << 3;
    const int bRow = (lane & 7) + ((lane >> 4) << 3);
    const int bK   = ((lane >> 3) & 1) << 3;

    for (int i = 0; i < NITER; i++) {
        asm volatile("cp.async.wait_group 2;" ::: "memory");
        __syncthreads();
        if (i + 3 < NITER) load(i + 3, (i + 3) & 3);
        else CPA_COMMIT();

        uint32_t abase = sb + (i & 3) * 16384;
        uint32_t bbase = abase + 8192;
#pragma unroll
        for (int kk = 0; kk < BK; kk += 16) {
            uint32_t a[2][4];
#pragma unroll
            for (int mi = 0; mi < 2; mi++) {
                int row = wm * 32 + mi * 16 + aRow;
                ldsm4(a[mi][0], a[mi][1], a[mi][2], a[mi][3],
                      abase + SWZ64(row * 64 + (kk + aK) * 2));
            }
            uint32_t b[4][4];
#pragma unroll
            for (int ng = 0; ng < 4; ng++) {
                int row = wn * 64 + ng * 16 + bRow;
                ldsm4(b[ng][0], b[ng][1], b[ng][2], b[ng][3],
                      bbase + SWZ64(row * 64 + (kk + bK) * 2));
            }
#pragma unroll
            for (int mi = 0; mi < 2; mi++)
#pragma unroll
                for (int ni = 0; ni < 8; ni++) {
                    int ng = ni >> 1, half = ni & 1;
                    mma16816(acc[mi][ni], a[mi][0], a[mi][1], a[mi][2], a[mi][3],
                             b[ng][half * 2], b[ng][half * 2 + 1]);
                }
        }
    }

    const int g = lane >> 2, tig = lane & 3;
#pragma unroll
    for (int mi = 0; mi < 2; mi++) {
        int r0 = rowBase + wm * 32 + mi * 16 + g;
        int r1 = r0 + 8;
#pragma unroll
        for (int ni = 0; ni < 8; ni++) {
            int c = colBase + wn * 64 + ni * 8 + tig * 2;
            if (c < N) {
                float bx = __ldg(&bias[c]), by = __ldg(&bias[c + 1]);
                if (HALF_OUT) {
                    __half* C = (__half*)Cv;
                    *reinterpret_cast<__half2*>(C + (size_t)r0 * N + c) =
                        __floats2half2_rn(acc[mi][ni][0] + bx, acc[mi][ni][1] + by);
                    *reinterpret_cast<__half2*>(C + (size_t)r1 * N + c) =
                        __floats2half2_rn(acc[mi][ni][2] + bx, acc[mi][ni][3] + by);
                } else {
                    float* C = (float*)Cv;
                    float2 v0 = make_float2(acc[mi][ni][0] + bx, acc[mi][ni][1] + by);
                    float2 v1 = make_float2(acc[mi][ni][2] + bx, acc[mi][ni][3] + by);
                    *reinterpret_cast<float2*>(C + (size_t)r0 * N + c) = v0;
                    *reinterpret_cast<float2*>(C + (size_t)r1 * N + c) = v1;
                }
            }
        }
    }
}

// fused value + query GEMM
__global__ __launch_bounds__(256, 2)
void gemm_vq(const float* __restrict__ biasV, float* __restrict__ CQ) {
    extern __shared__ char smem[];                  // 4 * 16384
    uint32_t sb = smem_u32(smem);
    int t = blockIdx.x;
    if (t < VTILES) {
        int rowBase = (t >> 1) * 128, colBase = (t & 1) * 128;
        gemm_body<true>(g_AV, g_WTV, biasV, g_v, DM, rowBase, colBase, sb);
    } else {
        t -= VTILES;
        int rowBase = (t / 3) * 128, colBase = (t % 3) * 128;
        gemm_body<false>(g_Abig, g_WTQ, g_bcat, CQ, PCOLS, rowBase, colBase, sb);
    }
}

// single GEMM (output projection)
__global__ __launch_bounds__(256, 2)
void gemm_single(const __nv_bfloat16* __restrict__ A, const __nv_bfloat16* __restrict__ Bt,
                 const float* __restrict__ bias, float* __restrict__ C, int N) {
    extern __shared__ char smem[];
    uint32_t sb = smem_u32(smem);
    int tilesX = (N + 127) / 128;
    int rowBase = (blockIdx.x / tilesX) * 128, colBase = (blockIdx.x % tilesX) * 128;
    gemm_body<false>(A, Bt, bias, C, N, rowBase, colBase, sb);
}

// ---------------- deformable sampling: 2 (q,h) per warp ----------------
__device__ __forceinline__ float tanh_approx(float x) {
    float r;
    asm("tanh.approx.f32 %0, %1;" : "=f"(r) : "f"(x));
    return r;
}

// warp handles gids (2w, 2w+1) in h-major order. Half-warp per gid.
// Tap prep: 16 lanes per gid (all 32 lanes busy). Gather: each lane covers
// 2 channels via __half2 (16 lanes x 4 B = one 64 B transaction per half-warp).
__global__ __launch_bounds__(256)
void sample_kernel(const float* __restrict__ refp) {
    __shared__ int   s_idx[8][2][64];
    __shared__ float s_w[8][2][64];

    const int warp = threadIdx.x >> 5;
    const int lane = threadIdx.x & 31;
    const int half = lane >> 4;                     // which gid of the pair
    const int li   = lane & 15;
    const int gid = (blockIdx.x * 8 + warp) * 2 + half;   // h-major: gid = h*32768 + bq
    const int h  = gid >> 15;
    const int bq = gid & 32767;
    const int b  = bq >> 13;                        // NQ=8192

    const float* __restrict__ P = g_P + (size_t)bq * PCOLS;
    const int hL = h * LL;

    {   // all 32 lanes do tap prep (li = sample index for this half's gid)
        const int l  = li >> 2, k = li & 3;
        const int kt = k >> 1,  kf = k & 1;
        const float t = tanh_approx(P[(hL + l) * 2 + kt]);
        const float f = tanh_approx(P[64 + (hL + l) * 2 + kf]);

        float e0 = P[128 + hL + 0], e1 = P[128 + hL + 1];
        float e2 = P[128 + hL + 2], e3 = P[128 + hL + 3];
        float mx = fmaxf(fmaxf(e0, e1), fmaxf(e2, e3));
        float x0e = __expf(e0 - mx), x1e = __expf(e1 - mx);
        float x2e = __expf(e2 - mx), x3e = __expf(e3 - mx);
        float lsum = x0e + x1e + x2e + x3e;
        float lwv = (l == 0 ? x0e : l == 1 ? x1e : l == 2 ? x2e : x3e);

        const float* pp = P + 160 + (hL + l) * 4;
        float p0 = pp[0], p1 = pp[1], p2 = pp[2], p3 = pp[3];
        float pm = fmaxf(fmaxf(p0, p1), fmaxf(p2, p3));
        float q0 = __expf(p0 - pm), q1 = __expf(p1 - pm);
        float q2 = __expf(p2 - pm), q3 = __expf(p3 - pm);
        float psum = q0 + q1 + q2 + q3;
        float pwv = (k == 0 ? q0 : k == 1 ? q1 : k == 2 ? q2 : q3);

        const float a = __fdividef(lwv * pwv, lsum * psum);

        const float* rp = refp + (size_t)bq * (LL * 2);
        const int   Wl = c_Wl[l];
        const int   start = c_lsi[l];
        const float fWl = (float)Wl;
        float lx = rp[l * 2 + 0] + t * c_inv[l];
        float ly = rp[l * 2 + 1] + f * c_inv[l];
        lx = fminf(fmaxf(lx, 0.f), 1.f);
        ly = fminf(fmaxf(ly, 0.f), 1.f);
        float x = lx * fWl - 0.5f;
        float y = ly * fWl - 0.5f;       // Hl == Wl for all levels
        float x0f = floorf(x), y0f = floorf(y);
        float wx1 = x - x0f, wy1 = y - y0f;
        float wx0 = 1.f - wx1, wy0 = 1.f - wy1;
        int x0 = (int)x0f, y0 = (int)y0f;

#pragma unroll
        for (int j = 0; j < 4; j++) {
            int xi = x0 + (j & 1), yi = y0 + (j >> 1);
            float w = a * ((j & 1) ? wx1 : wx0) * ((j >> 1) ? wy1 : wy0);
            bool valid = (xi >= 0) & (xi < Wl) & (yi >= 0) & (yi < Wl);
            int xc = min(max(xi, 0), Wl - 1);
            int yc = min(max(yi, 0), Wl - 1);
            s_idx[warp][half][li * 4 + j] = start + yc * Wl + xc;
            s_w[warp][half][li * 4 + j]   = valid ? w : 0.f;
        }
    }
    __syncwarp();

    // gather: lane covers channels (li*2, li*2+1) of its gid
    const __half2* __restrict__ vb = reinterpret_cast<const __half2*>(
        g_v + (size_t)b * NVV * DM + h * DHD + li * 2);
    float acc0 = 0.f, acc1 = 0.f;
#pragma unroll 16
    for (int t = 0; t < 64; t++) {
        float w = s_w[warp][half][t];
        float2 v = __half22float2(vb[(size_t)s_idx[warp][half][t] * (DM / 2)]);
        acc0 += w * v.x;
        acc1 += w * v.y;
    }

    // write split-bf16 pair into Abig for the output GEMM
    const int col = h * DHD + li * 2;
    __nv_bfloat16* p = g_Abig + (size_t)bq * ASTR + col;
    float h0 = __bfloat162float(__float2bfloat16(acc0));
    float h1 = __bfloat162float(__float2bfloat16(acc1));
    *reinterpret_cast<uint32_t*>(p)       = pack_bf2(h0, h1);
    *reinterpret_cast<uint32_t*>(p + 256) = pack_bf2(acc0 - h0, acc1 - h1);
}

// ---------------- launch ----------------
extern "C" void kernel_launch(void* const* d_in, const int* in_sizes, int n_in,
                              void* d_out, int out_size) {
    const float* query  = (const float*)d_in[0];
    const float* refp   = (const float*)d_in[1];
    const float* value  = (const float*)d_in[2];
    const float* W_time = (const float*)d_in[5];
    const float* b_time = (const float*)d_in[6];
    const float* W_freq = (const float*)d_in[7];
    const float* b_freq = (const float*)d_in[8];
    const float* W_lvl  = (const float*)d_in[9];
    const float* b_lvl  = (const float*)d_in[10];
    const float* W_pt   = (const float*)d_in[11];
    const float* b_pt   = (const float*)d_in[12];
    const float* W_v    = (const float*)d_in[13];
    const float* b_v    = (const float*)d_in[14];
    const float* W_o    = (const float*)d_in[15];
    const float* b_o    = (const float*)d_in[16];
    float* out = (float*)d_out;

    float *p_P;
    __nv_bfloat16 *p_Abig, *p_WTO;
    cudaGetSymbolAddress((void**)&p_P,    g_P);
    cudaGetSymbolAddress((void**)&p_Abig, g_Abig);
    cudaGetSymbolAddress((void**)&p_WTO,  g_WTO);

    const int GEMM_SMEM = 4 * 16384;   // 64 KB
    cudaFuncSetAttribute(gemm_vq,     cudaFuncAttributeMaxDynamicSharedMemorySize, GEMM_SMEM);
    cudaFuncSetAttribute(gemm_single, cudaFuncAttributeMaxDynamicSharedMemorySize, GEMM_SMEM);

    // 1) all conversions in ONE vectorized launch
    conv_all<<<CB_WQ, 256>>>(query, value, W_v, W_o,
                             W_time, b_time, W_freq, b_freq,
                             W_lvl, b_lvl, W_pt, b_pt);

    // 2) fused value + query GEMMs (340 + 768 = 1108 CTAs); value out = fp16 g_v
    gemm_vq<<<VTILES + 768, 256, GEMM_SMEM>>>(b_v, p_P);

    // 3) deformable sampling (2 gids/warp, half2 gather) -> split-bf16 mid in Abig
    sample_kernel<<<(BB * NQ * HH) / 16, 256>>>(refp);

    // 4) output GEMM: out = mid @ W_o + b_o   [32768 x 256]
    gemm_single<<<512, 256, GEMM_SMEM>>>(p_Abig, p_WTO, b_o, out, DM);
}

// round 12
// speedup vs baseline: 2.0581x; 1.0220x over previous
#include <cuda_runtime.h>
#include <cuda_bf16.h>
#include <cuda_fp16.h>
#include <cstdint>

// ---------------- problem constants ----------------
#define BB   4
#define NQ   8192
#define DM   256
#define HH   8
#define LL   4
#define DHD  32
#define NVV  5440
#define PCOLS 288
#define K3   768          // logical split-K: [A_hi | A_lo | A_hi] x [W_hi ; W_hi ; W_lo]
#define ASTR 512          // physical A storage: [A_hi | A_lo], 512 cols
#define NITER 24          // 768 / 32
#define BK   32
#define VTILES 340        // value GEMM: 170 row-tiles x 2 col-tiles

// conv_all block ranges (each block handles 1024 elements, 4 per thread)
#define CB_QA 8192                     // query convA: 8192*1024 = 8388608 elems
#define CB_VA (CB_QA + 5440)           // value convA: 5440*1024 = 5570560 elems
#define CB_WV (CB_VA + 96)             // W_v:   98304 elems
#define CB_WO (CB_WV + 96)             // W_o
#define CB_WQ (CB_WO + 96)             // Wcat (+ bias)

__device__ __constant__ int   c_Wl[LL]   = {64, 32, 16, 8};
__device__ __constant__ int   c_lsi[LL]  = {0, 4096, 5120, 5376};
__device__ __constant__ float c_inv[LL]  = {1.f/64.f, 1.f/32.f, 1.f/16.f, 1.f/8.f};

// ---------------- static device scratch ----------------
__device__ __nv_bfloat16 g_Abig[32768 * ASTR];  // split-bf16 A (query, then mid)
__device__ __nv_bfloat16 g_AV[BB * NVV * ASTR]; // split-bf16 A (value)
__device__ __nv_bfloat16 g_WTV[384 * K3];       // split W^T for W_v
__device__ __nv_bfloat16 g_WTO[384 * K3];       // split W^T for W_o
__device__ __nv_bfloat16 g_WTQ[384 * K3];       // split W^T for Wcat
__device__ __half g_v[BB * NVV * DM];           // projected value, fp16
__device__ float g_P[BB * NQ * PCOLS];
__device__ float g_bcat[PCOLS];

// ---------------- helpers ----------------
__device__ __forceinline__ uint32_t smem_u32(const void* p) {
    uint32_t a;
    asm("{ .reg .u64 t; cvta.to.shared.u64 t, %1; cvt.u32.u64 %0, t; }" : "=r"(a) : "l"(p));
    return a;
}
__device__ __forceinline__ void cpa16(uint32_t s, const void* g) {
    asm volatile("cp.async.cg.shared.global [%0], [%1], 16;" :: "r"(s), "l"(g));
}
#define CPA_COMMIT() asm volatile("cp.async.commit_group;" ::: "memory")
#define SWZ64(x) ((x) ^ (((x) >> 3) & 0x30))

__device__ __forceinline__ void ldsm4(uint32_t& r0, uint32_t& r1, uint32_t& r2, uint32_t& r3,
                                      uint32_t addr) {
    asm volatile("ldmatrix.sync.aligned.m8n8.x4.shared.b16 {%0,%1,%2,%3}, [%4];"
                 : "=r"(r0), "=r"(r1), "=r"(r2), "=r"(r3) : "r"(addr));
}
__device__ __forceinline__ void mma16816(float* c, uint32_t a0, uint32_t a1, uint32_t a2,
                                         uint32_t a3, uint32_t b0, uint32_t b1) {
    asm volatile("mma.sync.aligned.m16n8k16.row.col.f32.bf16.bf16.f32 "
                 "{%0,%1,%2,%3}, {%4,%5,%6,%7}, {%8,%9}, {%0,%1,%2,%3};"
                 : "+f"(c[0]), "+f"(c[1]), "+f"(c[2]), "+f"(c[3])
                 : "r"(a0), "r"(a1), "r"(a2), "r"(a3), "r"(b0), "r"(b1));
}

// chunk j (0..23) -> element offset inside the 512-col A storage
__device__ __forceinline__ int a_chunk_off(int j) {
    int jj = (j < 16) ? j : (j - 16);
    return ((jj & 8) ? 256 : 0) + (jj & 7) * BK;
}

// ---------------- one-launch vectorized conversions ----------------
__device__ __forceinline__ uint32_t pack_bf2(float a, float b) {
    uint32_t r;
    asm("cvt.rn.bf16x2.f32 %0, %2, %1;" : "=r"(r) : "f"(a), "f"(b));   // lo=a, hi=b
    return r;
}
__device__ __forceinline__ void splitA4(const float* __restrict__ A,
                                        __nv_bfloat16* __restrict__ dst, int i4) {
    int base = i4 * 4;
    int r = base >> 8, c = base & 255;
    float4 v = *reinterpret_cast<const float4*>(A + base);
    float hx = __bfloat162float(__float2bfloat16(v.x));
    float hy = __bfloat162float(__float2bfloat16(v.y));
    float hz = __bfloat162float(__float2bfloat16(v.z));
    float hw = __bfloat162float(__float2bfloat16(v.w));
    uint2 hi = make_uint2(pack_bf2(hx, hy), pack_bf2(hz, hw));
    uint2 lo = make_uint2(pack_bf2(v.x - hx, v.y - hy), pack_bf2(v.z - hz, v.w - hw));
    __nv_bfloat16* p = dst + (size_t)r * ASTR + c;
    *reinterpret_cast<uint2*>(p)       = hi;
    *reinterpret_cast<uint2*>(p + 256) = lo;
}
__device__ __forceinline__ void splitW4(const float* __restrict__ W,
                                        __nv_bfloat16* __restrict__ dst, int N, int i4) {
    int base = i4 * 4;
    int n = base >> 8, k = base & 255;        // 4 consecutive k, same n
    float v0 = (n < N) ? W[(k + 0) * N + n] : 0.f;
    float v1 = (n < N) ? W[(k + 1) * N + n] : 0.f;
    float v2 = (n < N) ? W[(k + 2) * N + n] : 0.f;
    float v3 = (n < N) ? W[(k + 3) * N + n] : 0.f;
    float h0 = __bfloat162float(__float2bfloat16(v0));
    float h1 = __bfloat162float(__float2bfloat16(v1));
    float h2 = __bfloat162float(__float2bfloat16(v2));
    float h3 = __bfloat162float(__float2bfloat16(v3));
    uint2 hi = make_uint2(pack_bf2(h0, h1), pack_bf2(h2, h3));
    uint2 lo = make_uint2(pack_bf2(v0 - h0, v1 - h1), pack_bf2(v2 - h2, v3 - h3));
    __nv_bfloat16* p = dst + (size_t)n * K3 + k;
    *reinterpret_cast<uint2*>(p)       = hi;
    *reinterpret_cast<uint2*>(p + 256) = hi;
    *reinterpret_cast<uint2*>(p + 512) = lo;
}

__global__ void conv_all(const float* __restrict__ query, const float* __restrict__ value,
                         const float* __restrict__ Wv, const float* __restrict__ Wo,
                         const float* __restrict__ Wt, const float* __restrict__ bt,
                         const float* __restrict__ Wf, const float* __restrict__ bf,
                         const float* __restrict__ Wl, const float* __restrict__ bl,
                         const float* __restrict__ Wp, const float* __restrict__ bp) {
    int blk = blockIdx.x;
    int tid = threadIdx.x;
    if (blk < CB_QA) {
        splitA4(query, g_Abig, blk * 256 + tid);
    } else if (blk < CB_VA) {
        splitA4(value, g_AV, (blk - CB_QA) * 256 + tid);
    } else if (blk < CB_WV) {
        splitW4(Wv, g_WTV, DM, (blk - CB_VA) * 256 + tid);
    } else if (blk < CB_WO) {
        splitW4(Wo, g_WTO, DM, (blk - CB_WV) * 256 + tid);
    } else {
        int i4 = (blk - CB_WO) * 256 + tid;
        int base = i4 * 4;
        int n = base >> 8, k = base & 255;
        float v[4];
#pragma unroll
        for (int j = 0; j < 4; j++) {
            int kk = k + j;
            float x = 0.f;
            if      (n < 64)    x = Wt[kk * 64  + n];
            else if (n < 128)   x = Wf[kk * 64  + (n - 64)];
            else if (n < 160)   x = Wl[kk * 32  + (n - 128)];
            else if (n < PCOLS) x = Wp[kk * 128 + (n - 160)];
            v[j] = x;
        }
        float h0 = __bfloat162float(__float2bfloat16(v[0]));
        float h1 = __bfloat162float(__float2bfloat16(v[1]));
        float h2 = __bfloat162float(__float2bfloat16(v[2]));
        float h3 = __bfloat162float(__float2bfloat16(v[3]));
        uint2 hi = make_uint2(pack_bf2(h0, h1), pack_bf2(h2, h3));
        uint2 lo = make_uint2(pack_bf2(v[0] - h0, v[1] - h1), pack_bf2(v[2] - h2, v[3] - h3));
        __nv_bfloat16* p = g_WTQ + (size_t)n * K3 + k;
        *reinterpret_cast<uint2*>(p)       = hi;
        *reinterpret_cast<uint2*>(p + 256) = hi;
        *reinterpret_cast<uint2*>(p + 512) = lo;
        if (base < PCOLS) {
#pragma unroll
            for (int j = 0; j < 4; j++) {
                int i = base + j;
                if (i < PCOLS) {
                    float bv;
                    if      (i < 64)  bv = bt[i];
                    else if (i < 128) bv = bf[i - 64];
                    else if (i < 160) bv = bl[i - 128];
                    else              bv = bp[i - 160];
                    g_bcat[i] = bv;
                }
            }
        }
    }
}

// ---------------- GEMM tile body: 128x128, BK=32, 4-stage cp.async ----------------
template <bool HALF_OUT>
__device__ __forceinline__ void gemm_body(const __nv_bfloat16* __restrict__ A,
                                          const __nv_bfloat16* __restrict__ Bt,
                                          const float* __restrict__ bias,
                                          void* __restrict__ Cv,
                                          int N, int rowBase, int colBase, uint32_t sb) {
    const int tid = threadIdx.x, wid = tid >> 5, lane = tid & 31;
    const int wm = wid >> 1, wn = wid & 1;

    auto load = [&](int j, int s) {
        uint32_t abase = sb + s * 16384;
        uint32_t bbase = abase + 8192;
        const __nv_bfloat16* ga = A  + (size_t)rowBase * ASTR + a_chunk_off(j);
        const __nv_bfloat16* gb = Bt + (size_t)colBase * K3 + j * BK;
#pragma unroll
        for (int it = 0; it < 2; it++) {
            int id = tid + it * 256;                // 0..511
            int r = id >> 2, c4 = (id & 3) * 16;
            uint32_t sw = SWZ64(r * 64 + c4);
            cpa16(abase + sw, (const char*)(ga + (size_t)r * ASTR) + c4);
            cpa16(bbase + sw, (const char*)(gb + (size_t)r * K3) + c4);
        }
        CPA_COMMIT();
    };

    float acc[2][8][4];
#pragma unroll
    for (int mi = 0; mi < 2; mi++)
#pragma unroll
        for (int ni = 0; ni < 8; ni++)
#pragma unroll
            for (int q = 0; q < 4; q++) acc[mi][ni][q] = 0.f;

    load(0, 0); load(1, 1); load(2, 2);

    const int aRow = (lane & 15);
    const int aK   = (lane >> 4) << 3;
    const int bRow = (lane & 7) + ((lane >> 4) << 3);
    const int bK   = ((lane >> 3) & 1) << 3;

    for (int i = 0; i < NITER; i++) {
        asm volatile("cp.async.wait_group 2;" ::: "memory");
        __syncthreads();
        if (i + 3 < NITER) load(i + 3, (i + 3) & 3);
        else CPA_COMMIT();

        uint32_t abase = sb + (i & 3) * 16384;
        uint32_t bbase = abase + 8192;
#pragma unroll
        for (int kk = 0; kk < BK; kk += 16) {
            uint32_t a[2][4];
#pragma unroll
            for (int mi = 0; mi < 2; mi++) {
                int row = wm * 32 + mi * 16 + aRow;
                ldsm4(a[mi][0], a[mi][1], a[mi][2], a[mi][3],
                      abase + SWZ64(row * 64 + (kk + aK) * 2));
            }
            uint32_t b[4][4];
#pragma unroll
            for (int ng = 0; ng < 4; ng++) {
                int row = wn * 64 + ng * 16 + bRow;
                ldsm4(b[ng][0], b[ng][1], b[ng][2], b[ng][3],
                      bbase + SWZ64(row * 64 + (kk + bK) * 2));
            }
#pragma unroll
            for (int mi = 0; mi < 2; mi++)
#pragma unroll
                for (int ni = 0; ni < 8; ni++) {
                    int ng = ni >> 1, half = ni & 1;
                    mma16816(acc[mi][ni], a[mi][0], a[mi][1], a[mi][2], a[mi][3],
                             b[ng][half * 2], b[ng][half * 2 + 1]);
                }
        }
    }

    const int g = lane >> 2, tig = lane & 3;
#pragma unroll
    for (int mi = 0; mi < 2; mi++) {
        int r0 = rowBase + wm * 32 + mi * 16 + g;
        int r1 = r0 + 8;
#pragma unroll
        for (int ni = 0; ni < 8; ni++) {
            int c = colBase + wn * 64 + ni * 8 + tig * 2;
            if (c < N) {
                float bx = __ldg(&bias[c]), by = __ldg(&bias[c + 1]);
                if (HALF_OUT) {
                    __half* C = (__half*)Cv;
                    *reinterpret_cast<__half2*>(C + (size_t)r0 * N + c) =
                        __floats2half2_rn(acc[mi][ni][0] + bx, acc[mi][ni][1] + by);
                    *reinterpret_cast<__half2*>(C + (size_t)r1 * N + c) =
                        __floats2half2_rn(acc[mi][ni][2] + bx, acc[mi][ni][3] + by);
                } else {
                    float* C = (float*)Cv;
                    float2 v0 = make_float2(acc[mi][ni][0] + bx, acc[mi][ni][1] + by);
                    float2 v1 = make_float2(acc[mi][ni][2] + bx, acc[mi][ni][3] + by);
                    *reinterpret_cast<float2*>(C + (size_t)r0 * N + c) = v0;
                    *reinterpret_cast<float2*>(C + (size_t)r1 * N + c) = v1;
                }
            }
        }
    }
}

// fused value + query GEMM
__global__ __launch_bounds__(256, 2)
void gemm_vq(const float* __restrict__ biasV, float* __restrict__ CQ) {
    extern __shared__ char smem[];                  // 4 * 16384
    uint32_t sb = smem_u32(smem);
    int t = blockIdx.x;
    if (t < VTILES) {
        int rowBase = (t >> 1) * 128, colBase = (t & 1) * 128;
        gemm_body<true>(g_AV, g_WTV, biasV, g_v, DM, rowBase, colBase, sb);
    } else {
        t -= VTILES;
        int rowBase = (t / 3) * 128, colBase = (t % 3) * 128;
        gemm_body<false>(g_Abig, g_WTQ, g_bcat, CQ, PCOLS, rowBase, colBase, sb);
    }
}

// single GEMM (output projection)
__global__ __launch_bounds__(256, 2)
void gemm_single(const __nv_bfloat16* __restrict__ A, const __nv_bfloat16* __restrict__ Bt,
                 const float* __restrict__ bias, float* __restrict__ C, int N) {
    extern __shared__ char smem[];
    uint32_t sb = smem_u32(smem);
    int tilesX = (N + 127) / 128;
    int rowBase = (blockIdx.x / tilesX) * 128, colBase = (blockIdx.x % tilesX) * 128;
    gemm_body<false>(A, Bt, bias, C, N, rowBase, colBase, sb);
}

// ---------------- deformable sampling: 4 (q,h) per warp ----------------
__device__ __forceinline__ float tanh_approx(float x) {
    float r;
    asm("tanh.approx.f32 %0, %1;" : "=f"(r) : "f"(x));
    return r;
}

// warp handles gids (4w .. 4w+3) in h-major order.
// Tap prep: 2 passes, each pass all 32 lanes cover 2 gids x 16 samples.
// Gather: 8 lanes per gid, each lane covers 4 channels via one 8 B load.
// Taps stored as packed float2 (weight, index) -> single LDS.64 in the loop.
__global__ __launch_bounds__(256)
void sample_kernel(const float* __restrict__ refp) {
    __shared__ float2 s_tap[8][4][64];    // [warp][gid-in-warp][tap] = (w, idx bits)

    const int warp = threadIdx.x >> 5;
    const int lane = threadIdx.x & 31;
    const int gbase = (blockIdx.x * 8 + warp) * 4;  // h-major: gid = h*32768 + bq

    // ---- tap prep: two passes, 32 lanes each covering 2 gids ----
#pragma unroll
    for (int jj = 0; jj < 2; jj++) {
        const int sub = (lane >> 4) + jj * 2;       // 0..3
        const int li  = lane & 15;                  // sample 0..15
        const int gid = gbase + sub;
        const int h  = gid >> 15;
        const int bq = gid & 32767;

        const float* __restrict__ P = g_P + (size_t)bq * PCOLS;
        const int hL = h * LL;

        const int l  = li >> 2, k = li & 3;
        const int kt = k >> 1,  kf = k & 1;
        const float t = tanh_approx(P[(hL + l) * 2 + kt]);
        const float f = tanh_approx(P[64 + (hL + l) * 2 + kf]);

        float e0 = P[128 + hL + 0], e1 = P[128 + hL + 1];
        float e2 = P[128 + hL + 2], e3 = P[128 + hL + 3];
        float mx = fmaxf(fmaxf(e0, e1), fmaxf(e2, e3));
        float x0e = __expf(e0 - mx), x1e = __expf(e1 - mx);
        float x2e = __expf(e2 - mx), x3e = __expf(e3 - mx);
        float lsum = x0e + x1e + x2e + x3e;
        float lwv = (l == 0 ? x0e : l == 1 ? x1e : l == 2 ? x2e : x3e);

        const float* pp = P + 160 + (hL + l) * 4;
        float p0 = pp[0], p1 = pp[1], p2 = pp[2], p3 = pp[3];
        float pm = fmaxf(fmaxf(p0, p1), fmaxf(p2, p3));
        float q0 = __expf(p0 - pm), q1 = __expf(p1 - pm);
        float q2 = __expf(p2 - pm), q3 = __expf(p3 - pm);
        float psum = q0 + q1 + q2 + q3;
        float pwv = (k == 0 ? q0 : k == 1 ? q1 : k == 2 ? q2 : q3);

        const float a = __fdividef(lwv * pwv, lsum * psum);

        const float* rp = refp + (size_t)bq * (LL * 2);
        const int   Wl = c_Wl[l];
        const int   start = c_lsi[l];
        const float fWl = (float)Wl;
        float lx = rp[l * 2 + 0] + t * c_inv[l];
        float ly = rp[l * 2 + 1] + f * c_inv[l];
        lx = fminf(fmaxf(lx, 0.f), 1.f);
        ly = fminf(fmaxf(ly, 0.f), 1.f);
        float x = lx * fWl - 0.5f;
        float y = ly * fWl - 0.5f;       // Hl == Wl for all levels
        float x0f = floorf(x), y0f = floorf(y);
        float wx1 = x - x0f, wy1 = y - y0f;
        float wx0 = 1.f - wx1, wy0 = 1.f - wy1;
        int x0 = (int)x0f, y0 = (int)y0f;

#pragma unroll
        for (int j = 0; j < 4; j++) {
            int xi = x0 + (j & 1), yi = y0 + (j >> 1);
            float w = a * ((j & 1) ? wx1 : wx0) * ((j >> 1) ? wy1 : wy0);
            bool valid = (xi >= 0) & (xi < Wl) & (yi >= 0) & (yi < Wl);
            int xc = min(max(xi, 0), Wl - 1);
            int yc = min(max(yi, 0), Wl - 1);
            s_tap[warp][sub][li * 4 + j] =
                make_float2(valid ? w : 0.f, __int_as_float(start + yc * Wl + xc));
        }
    }
    __syncwarp();

    // ---- gather: 8 lanes per gid, 4 channels per lane ----
    const int sub = lane >> 3;                      // 0..3
    const int ch  = (lane & 7) * 4;                 // channel base 0..28
    const int gid = gbase + sub;
    const int h  = gid >> 15;
    const int bq = gid & 32767;
    const int b  = bq >> 13;                        // NQ=8192

    const uint2* __restrict__ vb = reinterpret_cast<const uint2*>(
        g_v + (size_t)b * NVV * DM + h * DHD + ch);
    float acc0 = 0.f, acc1 = 0.f, acc2 = 0.f, acc3 = 0.f;
#pragma unroll 16
    for (int t = 0; t < 64; t++) {
        float2 tp = s_tap[warp][sub][t];
        uint2 raw = vb[(size_t)__float_as_int(tp.y) * (DM / 4)];
        float2 v01 = __half22float2(*reinterpret_cast<__half2*>(&raw.x));
        float2 v23 = __half22float2(*reinterpret_cast<__half2*>(&raw.y));
        acc0 += tp.x * v01.x;
        acc1 += tp.x * v01.y;
        acc2 += tp.x * v23.x;
        acc3 += tp.x * v23.y;
    }

    // write split-bf16 quad into Abig for the output GEMM
    const int col = h * DHD + ch;
    __nv_bfloat16* p = g_Abig + (size_t)bq * ASTR + col;
    float h0 = __bfloat162float(__float2bfloat16(acc0));
    float h1 = __bfloat162float(__float2bfloat16(acc1));
    float h2 = __bfloat162float(__float2bfloat16(acc2));
    float h3 = __bfloat162float(__float2bfloat16(acc3));
    *reinterpret_cast<uint2*>(p) =
        make_uint2(pack_bf2(h0, h1), pack_bf2(h2, h3));
    *reinterpret_cast<uint2*>(p + 256) =
        make_uint2(pack_bf2(acc0 - h0, acc1 - h1), pack_bf2(acc2 - h2, acc3 - h3));
}

// ---------------- launch ----------------
extern "C" void kernel_launch(void* const* d_in, const int* in_sizes, int n_in,
                              void* d_out, int out_size) {
    const float* query  = (const float*)d_in[0];
    const float* refp   = (const float*)d_in[1];
    const float* value  = (const float*)d_in[2];
    const float* W_time = (const float*)d_in[5];
    const float* b_time = (const float*)d_in[6];
    const float* W_freq = (const float*)d_in[7];
    const float* b_freq = (const float*)d_in[8];
    const float* W_lvl  = (const float*)d_in[9];
    const float* b_lvl  = (const float*)d_in[10];
    const float* W_pt   = (const float*)d_in[11];
    const float* b_pt   = (const float*)d_in[12];
    const float* W_v    = (const float*)d_in[13];
    const float* b_v    = (const float*)d_in[14];
    const float* W_o    = (const float*)d_in[15];
    const float* b_o    = (const float*)d_in[16];
    float* out = (float*)d_out;

    float *p_P;
    __nv_bfloat16 *p_Abig, *p_WTO;
    cudaGetSymbolAddress((void**)&p_P,    g_P);
    cudaGetSymbolAddress((void**)&p_Abig, g_Abig);
    cudaGetSymbolAddress((void**)&p_WTO,  g_WTO);

    const int GEMM_SMEM = 4 * 16384;   // 64 KB
    cudaFuncSetAttribute(gemm_vq,     cudaFuncAttributeMaxDynamicSharedMemorySize, GEMM_SMEM);
    cudaFuncSetAttribute(gemm_single, cudaFuncAttributeMaxDynamicSharedMemorySize, GEMM_SMEM);

    // 1) all conversions in ONE vectorized launch
    conv_all<<<CB_WQ, 256>>>(query, value, W_v, W_o,
                             W_time, b_time, W_freq, b_freq,
                             W_lvl, b_lvl, W_pt, b_pt);

    // 2) fused value + query GEMMs (340 + 768 = 1108 CTAs); value out = fp16 g_v
    gemm_vq<<<VTILES + 768, 256, GEMM_SMEM>>>(b_v, p_P);

    // 3) deformable sampling (4 gids/warp, 8B gathers) -> split-bf16 mid in Abig
    sample_kernel<<<(BB * NQ * HH) / 32, 256>>>(refp);

    // 4) output GEMM: out = mid @ W_o + b_o   [32768 x 256]
    gemm_single<<<512, 256, GEMM_SMEM>>>(p_Abig, p_WTO, b_o, out, DM);
}